// round 7
// baseline (speedup 1.0000x reference)
#include <cuda_runtime.h>
#include <cuda_bf16.h>
#include <math.h>
#include <stdint.h>

#define B_ 8
#define T_ 2048
#define C_ 2048
#define H_ 32
#define HS_ 64
#define M_ (B_*T_)   // 16384

typedef unsigned short ushort_t;

// ---------------- scratch (__device__ globals: allocation-free) ----------------
__device__ float g_tm [(size_t)M_*160];
__device__ float g_xr [(size_t)M_*C_];   // reused as bf16 hi/lo split of xr
__device__ float g_xk [(size_t)M_*C_];   // reused as bf16 hi/lo split of xk
__device__ float g_xv [(size_t)M_*C_];   // reused as bf16 hi/lo split of xv
__device__ float g_xw [(size_t)M_*C_];
__device__ float g_xv2[(size_t)M_*C_];
__device__ float g_r  [(size_t)M_*C_];
__device__ float g_k  [(size_t)M_*C_];
__device__ float g_v  [(size_t)M_*C_];
__device__ float g_v2 [(size_t)M_*C_];
__device__ float g_d  [(size_t)M_*C_];
__device__ float g_lw [(size_t)M_*64];
__device__ float g_lv2[(size_t)M_*64];
__device__ float g_yw [(size_t)M_*C_];

// bf16 hi/lo split scratch (xv2 split, later yln split)
__device__ ushort_t g_ah[(size_t)M_*C_];
__device__ ushort_t g_al[(size_t)M_*C_];

// transposed + split weights: [N, K] bf16 hi/lo
__device__ ushort_t g_wrh[(size_t)C_*C_];
__device__ ushort_t g_wrl[(size_t)C_*C_];
__device__ ushort_t g_wkh[(size_t)C_*C_];
__device__ ushort_t g_wkl[(size_t)C_*C_];
__device__ ushort_t g_wvh[(size_t)C_*C_];
__device__ ushort_t g_wvl[(size_t)C_*C_];
__device__ ushort_t g_woh[(size_t)C_*C_];
__device__ ushort_t g_wol[(size_t)C_*C_];

// ================= low-level helpers (base-target PTX only) =================
__device__ __forceinline__ uint32_t smem_u32(const void* p) {
    uint32_t a;
    asm("{ .reg .u64 t; cvta.to.shared.u64 t, %1; cvt.u32.u64 %0, t; }" : "=r"(a) : "l"(p));
    return a;
}
__device__ __forceinline__ void cp16(uint32_t dst, const void* src) {
    asm volatile("cp.async.cg.shared.global [%0], [%1], 16;" :: "r"(dst), "l"(src) : "memory");
}
#define CP_COMMIT() asm volatile("cp.async.commit_group;" ::: "memory")
#define CP_WAIT1()  asm volatile("cp.async.wait_group 1;"  ::: "memory")

__device__ __forceinline__ void ldsm_x4(uint32_t* r, uint32_t a) {
    asm volatile("ldmatrix.sync.aligned.m8n8.x4.shared.b16 {%0,%1,%2,%3}, [%4];"
        : "=r"(r[0]), "=r"(r[1]), "=r"(r[2]), "=r"(r[3]) : "r"(a));
}
__device__ __forceinline__ void mma16816(float* c, const uint32_t* a, const uint32_t* b) {
    asm volatile("mma.sync.aligned.m16n8k16.row.col.f32.bf16.bf16.f32 "
        "{%0,%1,%2,%3}, {%4,%5,%6,%7}, {%8,%9}, {%0,%1,%2,%3};"
        : "+f"(c[0]), "+f"(c[1]), "+f"(c[2]), "+f"(c[3])
        : "r"(a[0]), "r"(a[1]), "r"(a[2]), "r"(a[3]), "r"(b[0]), "r"(b[1]));
}

__device__ __forceinline__ void split1(float v, ushort_t& h, ushort_t& l) {
    __nv_bfloat16 hb = __float2bfloat16(v);
    h = __bfloat16_as_ushort(hb);
    l = __bfloat16_as_ushort(__float2bfloat16(v - __bfloat162float(hb)));
}

// ---------------- weight transpose + bf16 hi/lo split: T[n][k] = W[k][n] ----------------
__global__ void __launch_bounds__(256) wsplit_t(
    const float* __restrict__ W,
    ushort_t* __restrict__ Th, ushort_t* __restrict__ Tl)
{
    __shared__ float ts[32][33];
    int n0 = blockIdx.x * 32, k0 = blockIdx.y * 32;
    int tx = threadIdx.x & 31, ty = threadIdx.x >> 5;
#pragma unroll
    for (int e = 0; e < 4; e++)
        ts[ty + 8*e][tx] = W[(size_t)(k0 + ty + 8*e)*C_ + n0 + tx];
    __syncthreads();
#pragma unroll
    for (int e = 0; e < 4; e++) {
        int n = ty + 8*e;
        float v = ts[tx][n];
        ushort_t h, l;
        split1(v, h, l);
        Th[(size_t)(n0+n)*C_ + k0 + tx] = h;
        Tl[(size_t)(n0+n)*C_ + k0 + tx] = l;
    }
}

// ---------------- bf16x3 HMMA GEMM (round-4 proven shape) ----------------
// A hi/lo [M,K] row-major bf16, B = W^T hi/lo [N,K] row-major bf16, C fp32.
// CTA 128x128, 256 threads, warp tile 32x64, K-chunk 32, 3-stage cp.async pipe.
#define LDB     80          // padded row bytes (40 bf16): conflict-free ldmatrix
#define SZ_A    (128*LDB)   // 10240 per buffer
#define STAGE_B (4*SZ_A)    // Ah, Al, Bh, Bl
#define NSTAGE  3
#define GEMM_SMEM (NSTAGE*STAGE_B)   // 122880

__device__ __forceinline__ void gemm_load_stage(
    uint32_t sb, int s, const ushort_t* Ah, const ushort_t* Al,
    const ushort_t* Bh, const ushort_t* Bl, int m0, int n0, int kt, int tid)
{
    int k0 = kt * 32;
    uint32_t base = sb + s*STAGE_B;
#pragma unroll
    for (int e = 0; e < 2; e++) {
        int q = tid + 256*e;          // 0..511
        int row = q >> 2, c = q & 3;
        uint32_t d = base + row*LDB + c*16;
        size_t offA = (size_t)(m0 + row)*C_ + k0 + c*8;
        size_t offB = (size_t)(n0 + row)*C_ + k0 + c*8;
        cp16(d,           Ah + offA);
        cp16(d +   SZ_A,  Al + offA);
        cp16(d + 2*SZ_A,  Bh + offB);
        cp16(d + 3*SZ_A,  Bl + offB);
    }
    CP_COMMIT();
}

__global__ void __launch_bounds__(256, 1) gemm_bf3(
    const ushort_t* __restrict__ Ah, const ushort_t* __restrict__ Al,
    const ushort_t* __restrict__ Bh, const ushort_t* __restrict__ Bl,
    float* __restrict__ Cm)
{
    extern __shared__ char smem[];
    uint32_t sb = smem_u32(smem);
    int tid = threadIdx.x, lane = tid & 31, w = tid >> 5;
    int wm = w & 3, wn = w >> 2;           // 4 x 2 warp grid
    int m0 = blockIdx.y * 128, n0 = blockIdx.x * 128;

    float acc[2][8][4];
#pragma unroll
    for (int i = 0; i < 2; i++)
#pragma unroll
        for (int j = 0; j < 8; j++)
#pragma unroll
            for (int q = 0; q < 4; q++) acc[i][j][q] = 0.f;

    gemm_load_stage(sb, 0, Ah, Al, Bh, Bl, m0, n0, 0, tid);
    gemm_load_stage(sb, 1, Ah, Al, Bh, Bl, m0, n0, 1, tid);

    uint32_t a_off = (uint32_t)((wm*32 + (lane & 15))*LDB + (lane >> 4)*16);
    uint32_t b_off = (uint32_t)((wn*64 + (lane & 7) + ((lane >> 4) & 1)*8)*LDB
                                + ((lane >> 3) & 1)*16);

    const int NT = C_/32;   // 64
    for (int kt = 0; kt < NT; kt++) {
        int s = kt % NSTAGE;
        CP_WAIT1();
        __syncthreads();
        if (kt + 2 < NT)
            gemm_load_stage(sb, (kt+2) % NSTAGE, Ah, Al, Bh, Bl, m0, n0, kt+2, tid);

        uint32_t base = sb + s*STAGE_B;
#pragma unroll
        for (int kk = 0; kk < 2; kk++) {
            uint32_t ah[2][4], al[2][4];
#pragma unroll
            for (int mt = 0; mt < 2; mt++) {
                uint32_t addr = base + a_off + mt*16*LDB + kk*32;
                ldsm_x4(ah[mt], addr);
                ldsm_x4(al[mt], addr + SZ_A);
            }
#pragma unroll
            for (int g = 0; g < 4; g++) {
                uint32_t bh[4], bl[4];
                uint32_t addr = base + 2*SZ_A + b_off + g*16*LDB + kk*32;
                ldsm_x4(bh, addr);
                ldsm_x4(bl, addr + SZ_A);
#pragma unroll
                for (int mt = 0; mt < 2; mt++)
#pragma unroll
                    for (int n2 = 0; n2 < 2; n2++) {
                        float* a4 = acc[mt][g*2 + n2];
                        mma16816(a4, ah[mt], &bh[n2*2]);   // hh
                        mma16816(a4, ah[mt], &bl[n2*2]);   // h*lo
                        mma16816(a4, al[mt], &bh[n2*2]);   // lo*h
                    }
            }
        }
    }

    // epilogue: direct fp32 stores
#pragma unroll
    for (int mt = 0; mt < 2; mt++) {
        int r0 = m0 + wm*32 + mt*16 + (lane >> 2);
#pragma unroll
        for (int nt = 0; nt < 8; nt++) {
            int c0 = n0 + wn*64 + nt*8 + (lane & 3)*2;
            *(float2*)&Cm[(size_t)r0*C_ + c0] =
                make_float2(acc[mt][nt][0], acc[mt][nt][1]);
            *(float2*)&Cm[(size_t)(r0+8)*C_ + c0] =
                make_float2(acc[mt][nt][2], acc[mt][nt][3]);
        }
    }
}

// ---------------- skinny GEMM + tanh ----------------
template<int NS, bool FUSE>
__global__ void __launch_bounds__(256) skinny_tanh_gemm(
    const float* __restrict__ A, const float* __restrict__ W,
    float* __restrict__ out,
    const float* __restrict__ shift, const float* __restrict__ maax)
{
    __shared__ float As[32*68];
    __shared__ float Ws[32*NS];
    const int tid = threadIdx.x;
    const int m0  = blockIdx.x * 64;
    const int row = tid >> 2;
    const int cg  = tid & 3;

    float acc[NS/4];
#pragma unroll
    for (int i = 0; i < NS/4; i++) acc[i] = 0.f;

    for (int k0 = 0; k0 < C_; k0 += 32) {
#pragma unroll
        for (int e = 0; e < 2; e++) {
            int q  = tid + 256*e;
            int r  = q >> 3;
            int c4 = (q & 7) * 4;
            int m  = m0 + r;
            float4 val;
            if (FUSE) {
                float4 xv = *(const float4*)(A + (size_t)m*C_ + k0 + c4);
                int t = m & (T_-1);
                int b = m >> 11;
                float4 xp = (t > 0) ? *(const float4*)(A + (size_t)(m-1)*C_ + k0 + c4)
                                    : *(const float4*)(shift + (size_t)b*C_ + k0 + c4);
                float4 mx = *(const float4*)(maax + k0 + c4);
                val.x = xv.x + (xp.x - xv.x)*mx.x;
                val.y = xv.y + (xp.y - xv.y)*mx.y;
                val.z = xv.z + (xp.z - xv.z)*mx.z;
                val.w = xv.w + (xp.w - xv.w)*mx.w;
            } else {
                val = *(const float4*)(A + (size_t)m*C_ + k0 + c4);
            }
            As[(c4+0)*68 + r] = val.x;
            As[(c4+1)*68 + r] = val.y;
            As[(c4+2)*68 + r] = val.z;
            As[(c4+3)*68 + r] = val.w;
        }
        {
            const float4* src = (const float4*)(W + (size_t)k0*NS);
            for (int q = tid; q < 32*NS/4; q += 256)
                ((float4*)Ws)[q] = src[q];
        }
        __syncthreads();
#pragma unroll 8
        for (int k = 0; k < 32; k++) {
            float a = As[k*68 + row];
            const float* wrow = Ws + k*NS + cg*(NS/4);
#pragma unroll
            for (int j = 0; j < NS/16; j++) {
                float4 w4 = *(const float4*)(wrow + j*4);
                acc[j*4+0] = fmaf(a, w4.x, acc[j*4+0]);
                acc[j*4+1] = fmaf(a, w4.y, acc[j*4+1]);
                acc[j*4+2] = fmaf(a, w4.z, acc[j*4+2]);
                acc[j*4+3] = fmaf(a, w4.w, acc[j*4+3]);
            }
        }
        __syncthreads();
    }
    float* orow = out + (size_t)(m0+row)*NS + cg*(NS/4);
#pragma unroll
    for (int i = 0; i < NS/4; i++) orow[i] = tanhf(acc[i]);
}

// ---------------- fused 5-way mix, emits splits directly ----------------
#define MIX_SMEM (32*160*4 + 5*32*64*4)   // 61440
__global__ void __launch_bounds__(256) mix_all(
    const float* __restrict__ x, const float* __restrict__ shift,
    const float* __restrict__ tm, const float* __restrict__ w2,
    const float* __restrict__ maar, const float* __restrict__ maak,
    const float* __restrict__ maav, const float* __restrict__ maaw,
    const float* __restrict__ maav2,
    ushort_t* __restrict__ xrh, ushort_t* __restrict__ xrl,
    ushort_t* __restrict__ xkh, ushort_t* __restrict__ xkl,
    ushort_t* __restrict__ xvh, ushort_t* __restrict__ xvl,
    float* __restrict__ xw, float* __restrict__ xv2,
    ushort_t* __restrict__ xv2h, ushort_t* __restrict__ xv2l)
{
    extern __shared__ float ms[];
    float* tmf = ms;            // [32][160]
    float* w2f = ms + 32*160;   // [5][32][64]
    int tid = threadIdx.x;
    int m0 = blockIdx.y * 32;
    int c0 = blockIdx.x * 64;

#pragma unroll
    for (int q = tid; q < 32*160/4; q += 256) {
        int row = q / 40, c4 = (q % 40) * 4;
        *(float4*)&tmf[row*160 + c4] = *(const float4*)(tm + (size_t)(m0+row)*160 + c4);
    }
#pragma unroll
    for (int q = tid; q < 5*32*64/4; q += 256) {
        int fd = q / 16, c4 = (q % 16) * 4;    // fd = f*32+d
        *(float4*)&w2f[fd*64 + c4] = *(const float4*)(w2 + (size_t)fd*C_ + c0 + c4);
    }
    __syncthreads();

#pragma unroll
    for (int e = 0; e < 2; e++) {
        int p = tid + 256*e;
        int r  = p >> 4;
        int c4 = (p & 15) * 4;
        int m = m0 + r;
        int c = c0 + c4;
        float4 acc[5];
#pragma unroll
        for (int f = 0; f < 5; f++) acc[f] = make_float4(0.f,0.f,0.f,0.f);
        const float* trow = &tmf[r*160];
#pragma unroll
        for (int d = 0; d < 32; d++) {
#pragma unroll
            for (int f = 0; f < 5; f++) {
                float tv = trow[f*32 + d];
                float4 w4 = *(const float4*)&w2f[(f*32+d)*64 + c4];
                acc[f].x = fmaf(tv, w4.x, acc[f].x);
                acc[f].y = fmaf(tv, w4.y, acc[f].y);
                acc[f].z = fmaf(tv, w4.z, acc[f].z);
                acc[f].w = fmaf(tv, w4.w, acc[f].w);
            }
        }
        float4 xv4 = *(const float4*)(x + (size_t)m*C_ + c);
        int t = m & (T_-1), b = m >> 11;
        float4 xp = (t > 0) ? *(const float4*)(x + (size_t)(m-1)*C_ + c)
                            : *(const float4*)(shift + (size_t)b*C_ + c);
        float4 dx = make_float4(xp.x-xv4.x, xp.y-xv4.y, xp.z-xv4.z, xp.w-xv4.w);
        size_t base = (size_t)m*C_ + c;

#define MIX_VAL(maaP, fidx, comp, dcomp) \
        (xv4.comp + dx.comp * ((maaP)[c + dcomp] + acc[fidx].comp))

        {
            ushort4 h4, l4;
            split1(MIX_VAL(maar, 0, x, 0), h4.x, l4.x);
            split1(MIX_VAL(maar, 0, y, 1), h4.y, l4.y);
            split1(MIX_VAL(maar, 0, z, 2), h4.z, l4.z);
            split1(MIX_VAL(maar, 0, w, 3), h4.w, l4.w);
            *(ushort4*)(xrh + base) = h4;
            *(ushort4*)(xrl + base) = l4;
        }
        {
            ushort4 h4, l4;
            split1(MIX_VAL(maak, 1, x, 0), h4.x, l4.x);
            split1(MIX_VAL(maak, 1, y, 1), h4.y, l4.y);
            split1(MIX_VAL(maak, 1, z, 2), h4.z, l4.z);
            split1(MIX_VAL(maak, 1, w, 3), h4.w, l4.w);
            *(ushort4*)(xkh + base) = h4;
            *(ushort4*)(xkl + base) = l4;
        }
        {
            ushort4 h4, l4;
            split1(MIX_VAL(maav, 2, x, 0), h4.x, l4.x);
            split1(MIX_VAL(maav, 2, y, 1), h4.y, l4.y);
            split1(MIX_VAL(maav, 2, z, 2), h4.z, l4.z);
            split1(MIX_VAL(maav, 2, w, 3), h4.w, l4.w);
            *(ushort4*)(xvh + base) = h4;
            *(ushort4*)(xvl + base) = l4;
        }
        {
            float4 o = make_float4(MIX_VAL(maaw, 3, x, 0), MIX_VAL(maaw, 3, y, 1),
                                   MIX_VAL(maaw, 3, z, 2), MIX_VAL(maaw, 3, w, 3));
            *(float4*)(xw + base) = o;
        }
        {
            float v0 = MIX_VAL(maav2, 4, x, 0), v1 = MIX_VAL(maav2, 4, y, 1);
            float v2 = MIX_VAL(maav2, 4, z, 2), v3 = MIX_VAL(maav2, 4, w, 3);
            *(float4*)(xv2 + base) = make_float4(v0, v1, v2, v3);
            ushort4 h4, l4;
            split1(v0, h4.x, l4.x); split1(v1, h4.y, l4.y);
            split1(v2, h4.z, l4.z); split1(v3, h4.w, l4.w);
            *(ushort4*)(xv2h + base) = h4;
            *(ushort4*)(xv2l + base) = l4;
        }
#undef MIX_VAL
    }
}

// ---------------- small-K GEMM (K=64) with fused epilogues ----------------
template<int MODE>
__global__ void __launch_bounds__(256) smallk_gemm(
    const float* __restrict__ A, const float* __restrict__ W,
    const float* __restrict__ td, float* __restrict__ out1,
    float* __restrict__ karr)
{
    __shared__ float As[32*64];
    __shared__ float Ws[64*128];
    int tid = threadIdx.x;
    int m0 = blockIdx.y * 32, c0 = blockIdx.x * 128;
    {
        const float4* src = (const float4*)(A + (size_t)m0*64);
#pragma unroll
        for (int q = tid; q < 512; q += 256) ((float4*)As)[q] = src[q];
    }
#pragma unroll
    for (int e = 0; e < 8; e++) {
        int q = tid + 256*e;
        int kr = q >> 5, c4 = (q & 31) * 4;
        *(float4*)&Ws[kr*128 + c4] = *(const float4*)(W + (size_t)kr*C_ + c0 + c4);
    }
    __syncthreads();
    int ty = tid >> 4, tx = tid & 15;
    int r0 = ty * 2;
    float acc[2][8];
#pragma unroll
    for (int i = 0; i < 2; i++)
#pragma unroll
        for (int j = 0; j < 8; j++) acc[i][j] = 0.f;
#pragma unroll
    for (int k = 0; k < 64; k++) {
        float a0 = As[r0*64 + k];
        float a1 = As[(r0+1)*64 + k];
        float4 b0 = *(const float4*)&Ws[k*128 + tx*8];
        float4 b1 = *(const float4*)&Ws[k*128 + tx*8 + 4];
        float bv[8] = {b0.x,b0.y,b0.z,b0.w,b1.x,b1.y,b1.z,b1.w};
#pragma unroll
        for (int j = 0; j < 8; j++) {
            acc[0][j] = fmaf(a0, bv[j], acc[0][j]);
            acc[1][j] = fmaf(a1, bv[j], acc[1][j]);
        }
    }
#pragma unroll
    for (int rr = 0; rr < 2; rr++) {
        int m = m0 + r0 + rr;
        size_t base = (size_t)m*C_ + c0 + tx*8;
        if (MODE == 0) {
#pragma unroll
            for (int j = 0; j < 8; j++) {
                float w = td[c0 + tx*8 + j] + acc[rr][j];
                float dd = expf(-expf(w));
                out1[base + j] = dd;
                karr[base + j] *= (1.0f - dd);
            }
        } else {
#pragma unroll
            for (int j = 0; j < 8; j++) out1[base + j] += acc[rr][j];
        }
    }
}

// ---------------- WKV scan ----------------
__global__ void __launch_bounds__(64) wkv_scan(
    const float* __restrict__ rp, const float* __restrict__ kp,
    const float* __restrict__ vp, const float* __restrict__ dp,
    const float* __restrict__ S0, float* __restrict__ yp,
    float* __restrict__ Sout)
{
    int bh = blockIdx.x;
    int j = threadIdx.x;
    int b = bh >> 5, h = bh & (H_-1);
    float S[64];
    const float* s0 = S0 + (size_t)bh*HS_*HS_ + j;
#pragma unroll
    for (int i = 0; i < 64; i++) S[i] = s0[(size_t)i*64];
    __shared__ float4 skd[64];
    size_t idx = (size_t)b*T_*C_ + (size_t)h*64 + j;
    float rr = rp[idx], kk = kp[idx], dd = dp[idx], vv = vp[idx];
    for (int t = 0; t < T_; t++) {
        float rn = 0.f, kn = 0.f, dn = 0.f, vn = 0.f;
        if (t + 1 < T_) {
            size_t nx = idx + C_;
            rn = rp[nx]; kn = kp[nx]; dn = dp[nx]; vn = vp[nx];
        }
        skd[j] = make_float4(rr, kk, dd, 0.f);
        __syncthreads();
        float acc = 0.f;
#pragma unroll
        for (int i = 0; i < 64; i++) {
            float4 q = skd[i];
            acc  = fmaf(q.x, S[i], acc);
            S[i] = fmaf(q.z, S[i], q.y * vv);
        }
        yp[idx] = acc;
        __syncthreads();
        idx += C_;
        rr = rn; kk = kn; dd = dn; vv = vn;
    }
    float* so = Sout + (size_t)bh*HS_*HS_ + j;
#pragma unroll
    for (int i = 0; i < 64; i++) so[(size_t)i*64] = S[i];
}

// ---------------- fused add + LayerNorm, emits bf16 hi/lo split ----------------
__global__ void __launch_bounds__(256) ln_add_split(
    const float* __restrict__ a, const float* __restrict__ b,
    const float* __restrict__ lw, const float* __restrict__ lb,
    ushort_t* __restrict__ oh, ushort_t* __restrict__ ol)
{
    int m = blockIdx.x;
    int tid = threadIdx.x;
    const float* ar = a + (size_t)m*C_;
    const float* br = b + (size_t)m*C_;
    float vals[8];
    float s = 0.f, s2 = 0.f;
#pragma unroll
    for (int i = 0; i < 8; i++) {
        int c = tid + 256*i;
        float u = ar[c] + br[c];
        vals[i] = u; s += u; s2 = fmaf(u, u, s2);
    }
#pragma unroll
    for (int o = 16; o > 0; o >>= 1) {
        s  += __shfl_xor_sync(0xffffffffu, s,  o);
        s2 += __shfl_xor_sync(0xffffffffu, s2, o);
    }
    __shared__ float sa[8], sb2[8];
    if ((tid & 31) == 0) { sa[tid>>5] = s; sb2[tid>>5] = s2; }
    __syncthreads();
    s = 0.f; s2 = 0.f;
#pragma unroll
    for (int i = 0; i < 8; i++) { s += sa[i]; s2 += sb2[i]; }
    float mu  = s * (1.0f/C_);
    float var = s2 * (1.0f/C_) - mu*mu;
    float inv = rsqrtf(var + 1e-5f);
#pragma unroll
    for (int i = 0; i < 8; i++) {
        int c = tid + 256*i;
        float v = (vals[i] - mu)*inv*lw[c] + lb[c];
        ushort_t h, l;
        split1(v, h, l);
        oh[(size_t)m*C_ + c] = h;
        ol[(size_t)m*C_ + c] = l;
    }
}

__global__ void copy_xlast(const float* __restrict__ x, float* __restrict__ o)
{
    int i = blockIdx.x*256 + threadIdx.x;
    int b = i >> 11, c = i & (C_-1);
    o[i] = x[((size_t)b*T_ + (T_-1))*C_ + c];
}

// ---------------- launcher ----------------
extern "C" void kernel_launch(void* const* d_in, const int* in_sizes, int n_in,
                              void* d_out, int out_size)
{
    (void)in_sizes; (void)n_in;
    const float* x     = (const float*)d_in[0];
    const float* shift = (const float*)d_in[1];
    const float* wkv0  = (const float*)d_in[2];
    const float* maax  = (const float*)d_in[3];
    const float* maar  = (const float*)d_in[4];
    const float* maak  = (const float*)d_in[5];
    const float* maav  = (const float*)d_in[6];
    const float* maaw  = (const float*)d_in[7];
    const float* maav2 = (const float*)d_in[8];
    const float* w1    = (const float*)d_in[9];
    const float* w2    = (const float*)d_in[10];
    const float* tdec  = (const float*)d_in[11];
    const float* dw1   = (const float*)d_in[12];
    const float* dw2   = (const float*)d_in[13];
    const float* vw1   = (const float*)d_in[14];
    const float* vw2   = (const float*)d_in[15];
    const float* Wr    = (const float*)d_in[17];
    const float* Wk    = (const float*)d_in[18];
    const float* Wv    = (const float*)d_in[19];
    const float* Wo    = (const float*)d_in[20];
    const float* lnw   = (const float*)d_in[21];
    const float* lnb   = (const float*)d_in[22];
    float* out = (float*)d_out;

    float *tm,*xrf,*xkf,*xvf,*xw,*xv2,*rb,*kb,*vb,*v2b,*db,*lwv,*lv2,*yw;
    ushort_t *ah,*al,*wrh,*wrl,*wkh,*wkl,*wvh,*wvl,*woh,*wol;
    cudaGetSymbolAddress((void**)&tm,  g_tm);
    cudaGetSymbolAddress((void**)&xrf, g_xr);
    cudaGetSymbolAddress((void**)&xkf, g_xk);
    cudaGetSymbolAddress((void**)&xvf, g_xv);
    cudaGetSymbolAddress((void**)&xw,  g_xw);
    cudaGetSymbolAddress((void**)&xv2, g_xv2);
    cudaGetSymbolAddress((void**)&rb,  g_r);
    cudaGetSymbolAddress((void**)&kb,  g_k);
    cudaGetSymbolAddress((void**)&vb,  g_v);
    cudaGetSymbolAddress((void**)&v2b, g_v2);
    cudaGetSymbolAddress((void**)&db,  g_d);
    cudaGetSymbolAddress((void**)&lwv, g_lw);
    cudaGetSymbolAddress((void**)&lv2, g_lv2);
    cudaGetSymbolAddress((void**)&yw,  g_yw);
    cudaGetSymbolAddress((void**)&ah,  g_ah);
    cudaGetSymbolAddress((void**)&al,  g_al);
    cudaGetSymbolAddress((void**)&wrh, g_wrh);
    cudaGetSymbolAddress((void**)&wrl, g_wrl);
    cudaGetSymbolAddress((void**)&wkh, g_wkh);
    cudaGetSymbolAddress((void**)&wkl, g_wkl);
    cudaGetSymbolAddress((void**)&wvh, g_wvh);
    cudaGetSymbolAddress((void**)&wvl, g_wvl);
    cudaGetSymbolAddress((void**)&woh, g_woh);
    cudaGetSymbolAddress((void**)&wol, g_wol);

    ushort_t* xrh = (ushort_t*)xrf; ushort_t* xrl = xrh + (size_t)M_*C_;
    ushort_t* xkh = (ushort_t*)xkf; ushort_t* xkl = xkh + (size_t)M_*C_;
    ushort_t* xvh = (ushort_t*)xvf; ushort_t* xvl = xvh + (size_t)M_*C_;

    cudaFuncSetAttribute(gemm_bf3, cudaFuncAttributeMaxDynamicSharedMemorySize, GEMM_SMEM);
    cudaFuncSetAttribute(mix_all,  cudaFuncAttributeMaxDynamicSharedMemorySize, MIX_SMEM);

    // 0) weight transpose + bf16 split
    {
        dim3 gt(C_/32, C_/32);
        wsplit_t<<<gt,256>>>(Wr, wrh, wrl);
        wsplit_t<<<gt,256>>>(Wk, wkh, wkl);
        wsplit_t<<<gt,256>>>(Wv, wvh, wvl);
        wsplit_t<<<gt,256>>>(Wo, woh, wol);
    }

    // 1) LoRA-5 projection with fused token-shift mixing
    skinny_tanh_gemm<160, true><<<M_/64, 256>>>(x, w1, tm, shift, maax);

    // 2) fused 5-way mix (emits bf16 splits directly)
    {
        dim3 g(C_/64, M_/32);
        mix_all<<<g,256,MIX_SMEM>>>(x, shift, tm, w2,
                                    maar, maak, maav, maaw, maav2,
                                    xrh, xrl, xkh, xkl, xvh, xvl,
                                    xw, xv2, ah, al);
    }

    // 3) big projections via HMMA bf16x3
    dim3 gg(C_/128, M_/128);
    gemm_bf3<<<gg,256,GEMM_SMEM>>>(xrh, xrl, wrh, wrl, rb);
    gemm_bf3<<<gg,256,GEMM_SMEM>>>(xkh, xkl, wkh, wkl, kb);
    gemm_bf3<<<gg,256,GEMM_SMEM>>>(xvh, xvl, wvh, wvl, vb);
    gemm_bf3<<<gg,256,GEMM_SMEM>>>(ah,  al,  wvh, wvl, v2b);

    // 4) decay / value2 LoRAs
    skinny_tanh_gemm<64, false><<<M_/64, 256>>>(xw,  dw1, lwv, nullptr, nullptr);
    skinny_tanh_gemm<64, false><<<M_/64, 256>>>(xv2, vw1, lv2, nullptr, nullptr);
    {
        dim3 gs(C_/128, M_/32);
        smallk_gemm<0><<<gs,256>>>(lwv, dw2, tdec, db,  kb);
        smallk_gemm<1><<<gs,256>>>(lv2, vw2, nullptr, v2b, nullptr);
    }

    // 5) WKV scan, 6) add v2 + LayerNorm (split output), 7) output projection
    const size_t OFFS = (size_t)M_*C_;
    const size_t OFFX = OFFS + (size_t)B_*H_*HS_*HS_;
    bool full = (size_t)out_size >= OFFX + (size_t)B_*C_;
    float* Sout = full ? (out + OFFS) : tm;
    wkv_scan<<<B_*H_, 64>>>(rb, kb, vb, db, wkv0, yw, Sout);
    ln_add_split<<<M_, 256>>>(yw, v2b, lnw, lnb, ah, al);
    gemm_bf3<<<gg,256,GEMM_SMEM>>>(ah, al, woh, wol, out);
    if (full) copy_xlast<<<(B_*C_)/256, 256>>>(x, out + OFFX);
}

// round 8
// speedup vs baseline: 1.1329x; 1.1329x over previous
#include <cuda_runtime.h>
#include <cuda_bf16.h>
#include <math.h>
#include <stdint.h>

#define B_ 8
#define T_ 2048
#define C_ 2048
#define H_ 32
#define HS_ 64
#define M_ (B_*T_)   // 16384

typedef unsigned short ushort_t;

// ---------------- scratch (__device__ globals: allocation-free) ----------------
__device__ float g_tm [(size_t)M_*160];
__device__ float g_xr [(size_t)M_*C_];
__device__ float g_xk [(size_t)M_*C_];
__device__ float g_xv [(size_t)M_*C_];
__device__ float g_xw [(size_t)M_*C_];
__device__ float g_xv2[(size_t)M_*C_];
__device__ float g_r  [(size_t)M_*C_];
__device__ float g_k  [(size_t)M_*C_];
__device__ float g_v  [(size_t)M_*C_];
__device__ float g_v2 [(size_t)M_*C_];
__device__ float g_d  [(size_t)M_*C_];
__device__ float g_lw [(size_t)M_*64];
__device__ float g_lv2[(size_t)M_*64];
__device__ float g_yw [(size_t)M_*C_];

// activation bf16 hi/lo split (reused across the sequential GEMMs)
__device__ ushort_t g_ah[(size_t)M_*C_];
__device__ ushort_t g_al[(size_t)M_*C_];

// transposed + split weights: [N, K] bf16 hi/lo
__device__ ushort_t g_wrh[(size_t)C_*C_];
__device__ ushort_t g_wrl[(size_t)C_*C_];
__device__ ushort_t g_wkh[(size_t)C_*C_];
__device__ ushort_t g_wkl[(size_t)C_*C_];
__device__ ushort_t g_wvh[(size_t)C_*C_];
__device__ ushort_t g_wvl[(size_t)C_*C_];
__device__ ushort_t g_woh[(size_t)C_*C_];
__device__ ushort_t g_wol[(size_t)C_*C_];

// ================= low-level helpers (base-target PTX only) =================
__device__ __forceinline__ uint32_t smem_u32(const void* p) {
    uint32_t a;
    asm("{ .reg .u64 t; cvta.to.shared.u64 t, %1; cvt.u32.u64 %0, t; }" : "=r"(a) : "l"(p));
    return a;
}
__device__ __forceinline__ void cp16(uint32_t dst, const void* src) {
    asm volatile("cp.async.cg.shared.global [%0], [%1], 16;" :: "r"(dst), "l"(src) : "memory");
}
#define CP_COMMIT() asm volatile("cp.async.commit_group;" ::: "memory")
#define CP_WAIT1()  asm volatile("cp.async.wait_group 1;"  ::: "memory")

__device__ __forceinline__ void ldsm_x4(uint32_t* r, uint32_t a) {
    asm volatile("ldmatrix.sync.aligned.m8n8.x4.shared.b16 {%0,%1,%2,%3}, [%4];"
        : "=r"(r[0]), "=r"(r[1]), "=r"(r[2]), "=r"(r[3]) : "r"(a));
}
__device__ __forceinline__ void mma16816(float* c, const uint32_t* a, const uint32_t* b) {
    asm volatile("mma.sync.aligned.m16n8k16.row.col.f32.bf16.bf16.f32 "
        "{%0,%1,%2,%3}, {%4,%5,%6,%7}, {%8,%9}, {%0,%1,%2,%3};"
        : "+f"(c[0]), "+f"(c[1]), "+f"(c[2]), "+f"(c[3])
        : "r"(a[0]), "r"(a[1]), "r"(a[2]), "r"(a[3]), "r"(b[0]), "r"(b[1]));
}

__device__ __forceinline__ void cvt_split4(float4 v, uint2& hi, uint2& lo) {
    __nv_bfloat16 bx = __float2bfloat16(v.x), by = __float2bfloat16(v.y),
                  bz = __float2bfloat16(v.z), bw = __float2bfloat16(v.w);
    hi.x = (uint32_t)__bfloat16_as_ushort(bx) | ((uint32_t)__bfloat16_as_ushort(by) << 16);
    hi.y = (uint32_t)__bfloat16_as_ushort(bz) | ((uint32_t)__bfloat16_as_ushort(bw) << 16);
    __nv_bfloat16 lx = __float2bfloat16(v.x - __bfloat162float(bx));
    __nv_bfloat16 ly = __float2bfloat16(v.y - __bfloat162float(by));
    __nv_bfloat16 lz = __float2bfloat16(v.z - __bfloat162float(bz));
    __nv_bfloat16 lw = __float2bfloat16(v.w - __bfloat162float(bw));
    lo.x = (uint32_t)__bfloat16_as_ushort(lx) | ((uint32_t)__bfloat16_as_ushort(ly) << 16);
    lo.y = (uint32_t)__bfloat16_as_ushort(lz) | ((uint32_t)__bfloat16_as_ushort(lw) << 16);
}

// ---------------- weight transpose + bf16 hi/lo split: T[n][k] = W[k][n] ----------------
__global__ void __launch_bounds__(256) wsplit_t(
    const float* __restrict__ W,
    ushort_t* __restrict__ Th, ushort_t* __restrict__ Tl)
{
    __shared__ float ts[32][33];
    int n0 = blockIdx.x * 32, k0 = blockIdx.y * 32;
    int tx = threadIdx.x & 31, ty = threadIdx.x >> 5;
#pragma unroll
    for (int e = 0; e < 4; e++)
        ts[ty + 8*e][tx] = W[(size_t)(k0 + ty + 8*e)*C_ + n0 + tx];
    __syncthreads();
#pragma unroll
    for (int e = 0; e < 4; e++) {
        int n = ty + 8*e;
        float v = ts[tx][n];
        __nv_bfloat16 h = __float2bfloat16(v);
        Th[(size_t)(n0+n)*C_ + k0 + tx] = __bfloat16_as_ushort(h);
        Tl[(size_t)(n0+n)*C_ + k0 + tx] =
            __bfloat16_as_ushort(__float2bfloat16(v - __bfloat162float(h)));
    }
}

// ---------------- activation fp32 -> bf16 hi/lo split ----------------
__global__ void __launch_bounds__(256) asplit(
    const float* __restrict__ X, ushort_t* __restrict__ Hi, ushort_t* __restrict__ Lo)
{
    size_t i = ((size_t)blockIdx.x*256 + threadIdx.x) * 4;
    float4 v = *(const float4*)(X + i);
    uint2 h, l;
    cvt_split4(v, h, l);
    *(uint2*)(Hi + i) = h;
    *(uint2*)(Lo + i) = l;
}

// ---------------- bf16x3 HMMA GEMM: C[M,N] = A[M,K] @ B[K,N] ----------------
// A hi/lo [M,K] row-major bf16, B = W^T hi/lo [N,K] row-major bf16, C fp32.
// CTA 128x128, 256 threads, warp tile 32x64, K-chunk 32, 3-stage cp.async pipe.
#define LDB     80          // padded row bytes (40 bf16): conflict-free ldmatrix
#define SZ_A    (128*LDB)   // 10240 per buffer
#define STAGE_B (4*SZ_A)    // Ah, Al, Bh, Bl
#define NSTAGE  3
#define GEMM_SMEM (NSTAGE*STAGE_B)   // 122880

__device__ __forceinline__ void gemm_load_stage(
    uint32_t sb, int s, const ushort_t* Ah, const ushort_t* Al,
    const ushort_t* Bh, const ushort_t* Bl, int m0, int n0, int kt, int tid)
{
    int k0 = kt * 32;
    uint32_t base = sb + s*STAGE_B;
#pragma unroll
    for (int e = 0; e < 2; e++) {
        int q = tid + 256*e;          // 0..511
        int row = q >> 2, c = q & 3;
        uint32_t d = base + row*LDB + c*16;
        size_t offA = (size_t)(m0 + row)*C_ + k0 + c*8;
        size_t offB = (size_t)(n0 + row)*C_ + k0 + c*8;
        cp16(d,           Ah + offA);
        cp16(d +   SZ_A,  Al + offA);
        cp16(d + 2*SZ_A,  Bh + offB);
        cp16(d + 3*SZ_A,  Bl + offB);
    }
    CP_COMMIT();
}

__global__ void __launch_bounds__(256, 1) gemm_bf3(
    const ushort_t* __restrict__ Ah, const ushort_t* __restrict__ Al,
    const ushort_t* __restrict__ Bh, const ushort_t* __restrict__ Bl,
    float* __restrict__ Cm)
{
    extern __shared__ char smem[];
    uint32_t sb = smem_u32(smem);
    int tid = threadIdx.x, lane = tid & 31, w = tid >> 5;
    int wm = w & 3, wn = w >> 2;           // 4 x 2 warp grid
    int m0 = blockIdx.y * 128, n0 = blockIdx.x * 128;

    float acc[2][8][4];
#pragma unroll
    for (int i = 0; i < 2; i++)
#pragma unroll
        for (int j = 0; j < 8; j++)
#pragma unroll
            for (int q = 0; q < 4; q++) acc[i][j][q] = 0.f;

    gemm_load_stage(sb, 0, Ah, Al, Bh, Bl, m0, n0, 0, tid);
    gemm_load_stage(sb, 1, Ah, Al, Bh, Bl, m0, n0, 1, tid);

    // precomputed intra-warp ldmatrix offsets
    uint32_t a_off = (uint32_t)((wm*32 + (lane & 15))*LDB + (lane >> 4)*16);
    uint32_t b_off = (uint32_t)((wn*64 + (lane & 7) + ((lane >> 4) & 1)*8)*LDB
                                + ((lane >> 3) & 1)*16);

    for (int kt = 0; kt < C_/32; kt++) {
        int s = kt % NSTAGE;
        CP_WAIT1();
        __syncthreads();
        if (kt + 2 < C_/32)
            gemm_load_stage(sb, (kt+2) % NSTAGE, Ah, Al, Bh, Bl, m0, n0, kt+2, tid);

        uint32_t base = sb + s*STAGE_B;
#pragma unroll
        for (int kk = 0; kk < 2; kk++) {
            uint32_t ah[2][4], al[2][4], bh[4][4], bl[4][4];
#pragma unroll
            for (int mt = 0; mt < 2; mt++) {
                uint32_t addr = base + a_off + mt*16*LDB + kk*32;
                ldsm_x4(ah[mt], addr);
                ldsm_x4(al[mt], addr + SZ_A);
            }
#pragma unroll
            for (int g = 0; g < 4; g++) {
                uint32_t addr = base + 2*SZ_A + b_off + g*16*LDB + kk*32;
                ldsm_x4(bh[g], addr);
                ldsm_x4(bl[g], addr + SZ_A);
            }
#pragma unroll
            for (int mt = 0; mt < 2; mt++)
#pragma unroll
                for (int nt = 0; nt < 8; nt++) {
                    const uint32_t* bph = &bh[nt >> 1][(nt & 1)*2];
                    const uint32_t* bpl = &bl[nt >> 1][(nt & 1)*2];
                    mma16816(acc[mt][nt], ah[mt], bph);   // hh
                    mma16816(acc[mt][nt], ah[mt], bpl);   // h*lo
                    mma16816(acc[mt][nt], al[mt], bph);   // lo*h
                }
        }
    }

    // epilogue: direct fp32 stores
#pragma unroll
    for (int mt = 0; mt < 2; mt++) {
        int r0 = m0 + wm*32 + mt*16 + (lane >> 2);
#pragma unroll
        for (int nt = 0; nt < 8; nt++) {
            int c0 = n0 + wn*64 + nt*8 + (lane & 3)*2;
            *(float2*)&Cm[(size_t)r0*C_ + c0] =
                make_float2(acc[mt][nt][0], acc[mt][nt][1]);
            *(float2*)&Cm[(size_t)(r0+8)*C_ + c0] =
                make_float2(acc[mt][nt][2], acc[mt][nt][3]);
        }
    }
}

// ---------------- skinny GEMM + tanh ----------------
template<int NS, bool FUSE>
__global__ void __launch_bounds__(256) skinny_tanh_gemm(
    const float* __restrict__ A, const float* __restrict__ W,
    float* __restrict__ out,
    const float* __restrict__ shift, const float* __restrict__ maax)
{
    __shared__ float As[32*68];
    __shared__ float Ws[32*NS];
    const int tid = threadIdx.x;
    const int m0  = blockIdx.x * 64;
    const int row = tid >> 2;
    const int cg  = tid & 3;

    float acc[NS/4];
#pragma unroll
    for (int i = 0; i < NS/4; i++) acc[i] = 0.f;

    for (int k0 = 0; k0 < C_; k0 += 32) {
#pragma unroll
        for (int e = 0; e < 2; e++) {
            int q  = tid + 256*e;
            int r  = q >> 3;
            int c4 = (q & 7) * 4;
            int m  = m0 + r;
            float4 val;
            if (FUSE) {
                float4 xv = *(const float4*)(A + (size_t)m*C_ + k0 + c4);
                int t = m & (T_-1);
                int b = m >> 11;
                float4 xp = (t > 0) ? *(const float4*)(A + (size_t)(m-1)*C_ + k0 + c4)
                                    : *(const float4*)(shift + (size_t)b*C_ + k0 + c4);
                float4 mx = *(const float4*)(maax + k0 + c4);
                val.x = xv.x + (xp.x - xv.x)*mx.x;
                val.y = xv.y + (xp.y - xv.y)*mx.y;
                val.z = xv.z + (xp.z - xv.z)*mx.z;
                val.w = xv.w + (xp.w - xv.w)*mx.w;
            } else {
                val = *(const float4*)(A + (size_t)m*C_ + k0 + c4);
            }
            As[(c4+0)*68 + r] = val.x;
            As[(c4+1)*68 + r] = val.y;
            As[(c4+2)*68 + r] = val.z;
            As[(c4+3)*68 + r] = val.w;
        }
        {
            const float4* src = (const float4*)(W + (size_t)k0*NS);
            for (int q = tid; q < 32*NS/4; q += 256)
                ((float4*)Ws)[q] = src[q];
        }
        __syncthreads();
#pragma unroll 8
        for (int k = 0; k < 32; k++) {
            float a = As[k*68 + row];
            const float* wrow = Ws + k*NS + cg*(NS/4);
#pragma unroll
            for (int j = 0; j < NS/16; j++) {
                float4 w4 = *(const float4*)(wrow + j*4);
                acc[j*4+0] = fmaf(a, w4.x, acc[j*4+0]);
                acc[j*4+1] = fmaf(a, w4.y, acc[j*4+1]);
                acc[j*4+2] = fmaf(a, w4.z, acc[j*4+2]);
                acc[j*4+3] = fmaf(a, w4.w, acc[j*4+3]);
            }
        }
        __syncthreads();
    }
    float* orow = out + (size_t)(m0+row)*NS + cg*(NS/4);
#pragma unroll
    for (int i = 0; i < NS/4; i++) orow[i] = tanhf(acc[i]);
}

// ---------------- 5-way mix apply ----------------
__global__ void __launch_bounds__(256) mix_apply_f(
    const float* __restrict__ x, const float* __restrict__ shift,
    const float* __restrict__ tm, const float* __restrict__ w2,
    const float* __restrict__ maa, float* __restrict__ out, int f)
{
    __shared__ float tmf[32*32];
    __shared__ float w2f[32*64];
    int tid = threadIdx.x;
    int m0 = blockIdx.y * 32;
    int c0 = blockIdx.x * 64;
    {
        int r = tid >> 3, c4 = (tid & 7) * 4;
        *(float4*)&tmf[r*32 + c4] =
            *(const float4*)(tm + (size_t)(m0+r)*160 + f*32 + c4);
    }
#pragma unroll
    for (int e = 0; e < 2; e++) {
        int q = tid + 256*e;
        int d = q >> 4, c4 = (q & 15) * 4;
        *(float4*)&w2f[d*64 + c4] =
            *(const float4*)(w2 + (size_t)(f*32+d)*C_ + c0 + c4);
    }
    __syncthreads();
#pragma unroll
    for (int e = 0; e < 2; e++) {
        int p = tid + 256*e;
        int r  = p >> 4;
        int c4 = (p & 15) * 4;
        int m = m0 + r;
        int c = c0 + c4;
        float4 acc = make_float4(0.f,0.f,0.f,0.f);
#pragma unroll
        for (int d = 0; d < 32; d++) {
            float tv = tmf[r*32 + d];
            float4 w4 = *(const float4*)&w2f[d*64 + c4];
            acc.x = fmaf(tv, w4.x, acc.x);
            acc.y = fmaf(tv, w4.y, acc.y);
            acc.z = fmaf(tv, w4.z, acc.z);
            acc.w = fmaf(tv, w4.w, acc.w);
        }
        float4 xv = *(const float4*)(x + (size_t)m*C_ + c);
        int t = m & (T_-1), b = m >> 11;
        float4 xp = (t > 0) ? *(const float4*)(x + (size_t)(m-1)*C_ + c)
                            : *(const float4*)(shift + (size_t)b*C_ + c);
        float4 ma = *(const float4*)(maa + c);
        float4 o;
        o.x = xv.x + (xp.x - xv.x)*(ma.x + acc.x);
        o.y = xv.y + (xp.y - xv.y)*(ma.y + acc.y);
        o.z = xv.z + (xp.z - xv.z)*(ma.z + acc.z);
        o.w = xv.w + (xp.w - xv.w)*(ma.w + acc.w);
        *(float4*)(out + (size_t)m*C_ + c) = o;
    }
}

// ---------------- small-K GEMM (K=64) with fused epilogues ----------------
template<int MODE>
__global__ void __launch_bounds__(256) smallk_gemm(
    const float* __restrict__ A, const float* __restrict__ W,
    const float* __restrict__ td, float* __restrict__ out1,
    float* __restrict__ karr)
{
    __shared__ float As[32*64];
    __shared__ float Ws[64*128];
    int tid = threadIdx.x;
    int m0 = blockIdx.y * 32, c0 = blockIdx.x * 128;
    {
        const float4* src = (const float4*)(A + (size_t)m0*64);
#pragma unroll
        for (int q = tid; q < 512; q += 256) ((float4*)As)[q] = src[q];
    }
#pragma unroll
    for (int e = 0; e < 8; e++) {
        int q = tid + 256*e;
        int kr = q >> 5, c4 = (q & 31) * 4;
        *(float4*)&Ws[kr*128 + c4] = *(const float4*)(W + (size_t)kr*C_ + c0 + c4);
    }
    __syncthreads();
    int ty = tid >> 4, tx = tid & 15;
    int r0 = ty * 2;
    float acc[2][8];
#pragma unroll
    for (int i = 0; i < 2; i++)
#pragma unroll
        for (int j = 0; j < 8; j++) acc[i][j] = 0.f;
#pragma unroll
    for (int k = 0; k < 64; k++) {
        float a0 = As[r0*64 + k];
        float a1 = As[(r0+1)*64 + k];
        float4 b0 = *(const float4*)&Ws[k*128 + tx*8];
        float4 b1 = *(const float4*)&Ws[k*128 + tx*8 + 4];
        float bv[8] = {b0.x,b0.y,b0.z,b0.w,b1.x,b1.y,b1.z,b1.w};
#pragma unroll
        for (int j = 0; j < 8; j++) {
            acc[0][j] = fmaf(a0, bv[j], acc[0][j]);
            acc[1][j] = fmaf(a1, bv[j], acc[1][j]);
        }
    }
#pragma unroll
    for (int rr = 0; rr < 2; rr++) {
        int m = m0 + r0 + rr;
        size_t base = (size_t)m*C_ + c0 + tx*8;
        if (MODE == 0) {
#pragma unroll
            for (int j = 0; j < 8; j++) {
                float w = td[c0 + tx*8 + j] + acc[rr][j];
                float dd = expf(-expf(w));
                out1[base + j] = dd;
                karr[base + j] *= (1.0f - dd);
            }
        } else {
#pragma unroll
            for (int j = 0; j < 8; j++) out1[base + j] += acc[rr][j];
        }
    }
}

// ---------------- WKV scan ----------------
__global__ void __launch_bounds__(64) wkv_scan(
    const float* __restrict__ rp, const float* __restrict__ kp,
    const float* __restrict__ vp, const float* __restrict__ dp,
    const float* __restrict__ S0, float* __restrict__ yp,
    float* __restrict__ Sout)
{
    int bh = blockIdx.x;
    int j = threadIdx.x;
    int b = bh >> 5, h = bh & (H_-1);
    float S[64];
    const float* s0 = S0 + (size_t)bh*HS_*HS_ + j;
#pragma unroll
    for (int i = 0; i < 64; i++) S[i] = s0[(size_t)i*64];
    __shared__ float4 skd[64];
    size_t idx = (size_t)b*T_*C_ + (size_t)h*64 + j;
    float rr = rp[idx], kk = kp[idx], dd = dp[idx], vv = vp[idx];
    for (int t = 0; t < T_; t++) {
        float rn = 0.f, kn = 0.f, dn = 0.f, vn = 0.f;
        if (t + 1 < T_) {
            size_t nx = idx + C_;
            rn = rp[nx]; kn = kp[nx]; dn = dp[nx]; vn = vp[nx];
        }
        skd[j] = make_float4(rr, kk, dd, 0.f);
        __syncthreads();
        float acc = 0.f;
#pragma unroll
        for (int i = 0; i < 64; i++) {
            float4 q = skd[i];
            acc  = fmaf(q.x, S[i], acc);
            S[i] = fmaf(q.z, S[i], q.y * vv);
        }
        yp[idx] = acc;
        __syncthreads();
        idx += C_;
        rr = rn; kk = kn; dd = dn; vv = vn;
    }
    float* so = Sout + (size_t)bh*HS_*HS_ + j;
#pragma unroll
    for (int i = 0; i < 64; i++) so[(size_t)i*64] = S[i];
}

// ---------------- fused add + LayerNorm, emits bf16 hi/lo split ----------------
__global__ void __launch_bounds__(256) ln_add_split(
    const float* __restrict__ a, const float* __restrict__ b,
    const float* __restrict__ lw, const float* __restrict__ lb,
    ushort_t* __restrict__ oh, ushort_t* __restrict__ ol)
{
    int m = blockIdx.x;
    int tid = threadIdx.x;
    const float* ar = a + (size_t)m*C_;
    const float* br = b + (size_t)m*C_;
    float vals[8];
    float s = 0.f, s2 = 0.f;
#pragma unroll
    for (int i = 0; i < 8; i++) {
        int c = tid + 256*i;
        float u = ar[c] + br[c];
        vals[i] = u; s += u; s2 = fmaf(u, u, s2);
    }
#pragma unroll
    for (int o = 16; o > 0; o >>= 1) {
        s  += __shfl_xor_sync(0xffffffffu, s,  o);
        s2 += __shfl_xor_sync(0xffffffffu, s2, o);
    }
    __shared__ float sa[8], sb2[8];
    if ((tid & 31) == 0) { sa[tid>>5] = s; sb2[tid>>5] = s2; }
    __syncthreads();
    s = 0.f; s2 = 0.f;
#pragma unroll
    for (int i = 0; i < 8; i++) { s += sa[i]; s2 += sb2[i]; }
    float mu  = s * (1.0f/C_);
    float var = s2 * (1.0f/C_) - mu*mu;
    float inv = rsqrtf(var + 1e-5f);
#pragma unroll
    for (int i = 0; i < 8; i++) {
        int c = tid + 256*i;
        float v = (vals[i] - mu)*inv*lw[c] + lb[c];
        __nv_bfloat16 hb = __float2bfloat16(v);
        oh[(size_t)m*C_ + c] = __bfloat16_as_ushort(hb);
        ol[(size_t)m*C_ + c] =
            __bfloat16_as_ushort(__float2bfloat16(v - __bfloat162float(hb)));
    }
}

__global__ void copy_xlast(const float* __restrict__ x, float* __restrict__ o)
{
    int i = blockIdx.x*256 + threadIdx.x;
    int b = i >> 11, c = i & (C_-1);
    o[i] = x[((size_t)b*T_ + (T_-1))*C_ + c];
}

// ---------------- launcher ----------------
extern "C" void kernel_launch(void* const* d_in, const int* in_sizes, int n_in,
                              void* d_out, int out_size)
{
    (void)in_sizes; (void)n_in;
    const float* x     = (const float*)d_in[0];
    const float* shift = (const float*)d_in[1];
    const float* wkv0  = (const float*)d_in[2];
    const float* maax  = (const float*)d_in[3];
    const float* maar  = (const float*)d_in[4];
    const float* maak  = (const float*)d_in[5];
    const float* maav  = (const float*)d_in[6];
    const float* maaw  = (const float*)d_in[7];
    const float* maav2 = (const float*)d_in[8];
    const float* w1    = (const float*)d_in[9];
    const float* w2    = (const float*)d_in[10];
    const float* tdec  = (const float*)d_in[11];
    const float* dw1   = (const float*)d_in[12];
    const float* dw2   = (const float*)d_in[13];
    const float* vw1   = (const float*)d_in[14];
    const float* vw2   = (const float*)d_in[15];
    const float* Wr    = (const float*)d_in[17];
    const float* Wk    = (const float*)d_in[18];
    const float* Wv    = (const float*)d_in[19];
    const float* Wo    = (const float*)d_in[20];
    const float* lnw   = (const float*)d_in[21];
    const float* lnb   = (const float*)d_in[22];
    float* out = (float*)d_out;

    float *tm,*xr,*xk,*xv,*xw,*xv2,*rb,*kb,*vb,*v2b,*db,*lwv,*lv2,*yw;
    ushort_t *ah,*al,*wrh,*wrl,*wkh,*wkl,*wvh,*wvl,*woh,*wol;
    cudaGetSymbolAddress((void**)&tm,  g_tm);
    cudaGetSymbolAddress((void**)&xr,  g_xr);
    cudaGetSymbolAddress((void**)&xk,  g_xk);
    cudaGetSymbolAddress((void**)&xv,  g_xv);
    cudaGetSymbolAddress((void**)&xw,  g_xw);
    cudaGetSymbolAddress((void**)&xv2, g_xv2);
    cudaGetSymbolAddress((void**)&rb,  g_r);
    cudaGetSymbolAddress((void**)&kb,  g_k);
    cudaGetSymbolAddress((void**)&vb,  g_v);
    cudaGetSymbolAddress((void**)&v2b, g_v2);
    cudaGetSymbolAddress((void**)&db,  g_d);
    cudaGetSymbolAddress((void**)&lwv, g_lw);
    cudaGetSymbolAddress((void**)&lv2, g_lv2);
    cudaGetSymbolAddress((void**)&yw,  g_yw);
    cudaGetSymbolAddress((void**)&ah,  g_ah);
    cudaGetSymbolAddress((void**)&al,  g_al);
    cudaGetSymbolAddress((void**)&wrh, g_wrh);
    cudaGetSymbolAddress((void**)&wrl, g_wrl);
    cudaGetSymbolAddress((void**)&wkh, g_wkh);
    cudaGetSymbolAddress((void**)&wkl, g_wkl);
    cudaGetSymbolAddress((void**)&wvh, g_wvh);
    cudaGetSymbolAddress((void**)&wvl, g_wvl);
    cudaGetSymbolAddress((void**)&woh, g_woh);
    cudaGetSymbolAddress((void**)&wol, g_wol);

    cudaFuncSetAttribute(gemm_bf3, cudaFuncAttributeMaxDynamicSharedMemorySize, GEMM_SMEM);

    // 0) weight transpose + bf16 split
    {
        dim3 gt(C_/32, C_/32);
        wsplit_t<<<gt,256>>>(Wr, wrh, wrl);
        wsplit_t<<<gt,256>>>(Wk, wkh, wkl);
        wsplit_t<<<gt,256>>>(Wv, wvh, wvl);
        wsplit_t<<<gt,256>>>(Wo, woh, wol);
    }

    // 1) LoRA-5 projection with fused token-shift mixing
    skinny_tanh_gemm<160, true><<<M_/64, 256>>>(x, w1, tm, shift, maax);

    // 2) 5-way mix
    {
        dim3 g(C_/64, M_/32);
        mix_apply_f<<<g,256>>>(x, shift, tm, w2, maar,  xr,  0);
        mix_apply_f<<<g,256>>>(x, shift, tm, w2, maak,  xk,  1);
        mix_apply_f<<<g,256>>>(x, shift, tm, w2, maav,  xv,  2);
        mix_apply_f<<<g,256>>>(x, shift, tm, w2, maaw,  xw,  3);
        mix_apply_f<<<g,256>>>(x, shift, tm, w2, maav2, xv2, 4);
    }

    // 3) big projections via HMMA bf16x3 (split activation, then GEMM)
    const int NSPLIT = (int)(((size_t)M_*C_/4) / 256);
    dim3 gg(C_/128, M_/128);
    asplit<<<NSPLIT,256>>>(xr, ah, al);
    gemm_bf3<<<gg,256,GEMM_SMEM>>>(ah, al, wrh, wrl, rb);
    asplit<<<NSPLIT,256>>>(xk, ah, al);
    gemm_bf3<<<gg,256,GEMM_SMEM>>>(ah, al, wkh, wkl, kb);
    asplit<<<NSPLIT,256>>>(xv, ah, al);
    gemm_bf3<<<gg,256,GEMM_SMEM>>>(ah, al, wvh, wvl, vb);
    asplit<<<NSPLIT,256>>>(xv2, ah, al);
    gemm_bf3<<<gg,256,GEMM_SMEM>>>(ah, al, wvh, wvl, v2b);

    // 4) decay / value2 LoRAs
    skinny_tanh_gemm<64, false><<<M_/64, 256>>>(xw,  dw1, lwv, nullptr, nullptr);
    skinny_tanh_gemm<64, false><<<M_/64, 256>>>(xv2, vw1, lv2, nullptr, nullptr);
    {
        dim3 gs(C_/128, M_/32);
        smallk_gemm<0><<<gs,256>>>(lwv, dw2, tdec, db,  kb);
        smallk_gemm<1><<<gs,256>>>(lv2, vw2, nullptr, v2b, nullptr);
    }

    // 5) WKV scan, 6) add v2 + LayerNorm (split output), 7) output projection
    const size_t OFFS = (size_t)M_*C_;
    const size_t OFFX = OFFS + (size_t)B_*H_*HS_*HS_;
    bool full = (size_t)out_size >= OFFX + (size_t)B_*C_;
    float* Sout = full ? (out + OFFS) : tm;
    wkv_scan<<<B_*H_, 64>>>(rb, kb, vb, db, wkv0, yw, Sout);
    ln_add_split<<<M_, 256>>>(yw, v2b, lnw, lnb, ah, al);
    gemm_bf3<<<gg,256,GEMM_SMEM>>>(ah, al, woh, wol, out);
    if (full) copy_xlast<<<(B_*C_)/256, 256>>>(x, out + OFFX);
}

// round 9
// speedup vs baseline: 1.2258x; 1.0820x over previous
#include <cuda_runtime.h>
#include <cuda_bf16.h>
#include <math.h>
#include <stdint.h>

#define B_ 8
#define T_ 2048
#define C_ 2048
#define H_ 32
#define HS_ 64
#define M_ (B_*T_)   // 16384

typedef unsigned short ushort_t;

// ---------------- scratch (__device__ globals: allocation-free) ----------------
__device__ float g_tm [(size_t)M_*160];
__device__ float g_xr [(size_t)M_*C_];
__device__ float g_xk [(size_t)M_*C_];
__device__ float g_xv [(size_t)M_*C_];
__device__ float g_xw [(size_t)M_*C_];
__device__ float g_xv2[(size_t)M_*C_];
__device__ float g_r  [(size_t)M_*C_];
__device__ float g_k  [(size_t)M_*C_];
__device__ float g_v  [(size_t)M_*C_];
__device__ float g_v2 [(size_t)M_*C_];
__device__ float g_d  [(size_t)M_*C_];
__device__ float g_lw [(size_t)M_*64];
__device__ float g_lv2[(size_t)M_*64];
__device__ float g_yw [(size_t)M_*C_];

// activation bf16 hi/lo split (reused across the sequential GEMMs)
__device__ ushort_t g_ah[(size_t)M_*C_];
__device__ ushort_t g_al[(size_t)M_*C_];

// transposed + split weights: [N, K] bf16 hi/lo
__device__ ushort_t g_wrh[(size_t)C_*C_];
__device__ ushort_t g_wrl[(size_t)C_*C_];
__device__ ushort_t g_wkh[(size_t)C_*C_];
__device__ ushort_t g_wkl[(size_t)C_*C_];
__device__ ushort_t g_wvh[(size_t)C_*C_];
__device__ ushort_t g_wvl[(size_t)C_*C_];
__device__ ushort_t g_woh[(size_t)C_*C_];
__device__ ushort_t g_wol[(size_t)C_*C_];

// ================= low-level helpers (base-target PTX only) =================
__device__ __forceinline__ uint32_t smem_u32(const void* p) {
    uint32_t a;
    asm("{ .reg .u64 t; cvta.to.shared.u64 t, %1; cvt.u32.u64 %0, t; }" : "=r"(a) : "l"(p));
    return a;
}
__device__ __forceinline__ void cp16(uint32_t dst, const void* src) {
    asm volatile("cp.async.cg.shared.global [%0], [%1], 16;" :: "r"(dst), "l"(src) : "memory");
}
#define CP_COMMIT() asm volatile("cp.async.commit_group;" ::: "memory")
#define CP_WAIT1()  asm volatile("cp.async.wait_group 1;"  ::: "memory")

__device__ __forceinline__ void ldsm_x4(uint32_t* r, uint32_t a) {
    asm volatile("ldmatrix.sync.aligned.m8n8.x4.shared.b16 {%0,%1,%2,%3}, [%4];"
        : "=r"(r[0]), "=r"(r[1]), "=r"(r[2]), "=r"(r[3]) : "r"(a));
}
__device__ __forceinline__ void mma16816(float* c, const uint32_t* a, const uint32_t* b) {
    asm volatile("mma.sync.aligned.m16n8k16.row.col.f32.bf16.bf16.f32 "
        "{%0,%1,%2,%3}, {%4,%5,%6,%7}, {%8,%9}, {%0,%1,%2,%3};"
        : "+f"(c[0]), "+f"(c[1]), "+f"(c[2]), "+f"(c[3])
        : "r"(a[0]), "r"(a[1]), "r"(a[2]), "r"(a[3]), "r"(b[0]), "r"(b[1]));
}

__device__ __forceinline__ void cvt_split4(float4 v, uint2& hi, uint2& lo) {
    __nv_bfloat16 bx = __float2bfloat16(v.x), by = __float2bfloat16(v.y),
                  bz = __float2bfloat16(v.z), bw = __float2bfloat16(v.w);
    hi.x = (uint32_t)__bfloat16_as_ushort(bx) | ((uint32_t)__bfloat16_as_ushort(by) << 16);
    hi.y = (uint32_t)__bfloat16_as_ushort(bz) | ((uint32_t)__bfloat16_as_ushort(bw) << 16);
    __nv_bfloat16 lx = __float2bfloat16(v.x - __bfloat162float(bx));
    __nv_bfloat16 ly = __float2bfloat16(v.y - __bfloat162float(by));
    __nv_bfloat16 lz = __float2bfloat16(v.z - __bfloat162float(bz));
    __nv_bfloat16 lw = __float2bfloat16(v.w - __bfloat162float(bw));
    lo.x = (uint32_t)__bfloat16_as_ushort(lx) | ((uint32_t)__bfloat16_as_ushort(ly) << 16);
    lo.y = (uint32_t)__bfloat16_as_ushort(lz) | ((uint32_t)__bfloat16_as_ushort(lw) << 16);
}

// ---------------- weight transpose + bf16 hi/lo split: T[n][k] = W[k][n] ----------------
__global__ void __launch_bounds__(256) wsplit_t(
    const float* __restrict__ W,
    ushort_t* __restrict__ Th, ushort_t* __restrict__ Tl)
{
    __shared__ float ts[32][33];
    int n0 = blockIdx.x * 32, k0 = blockIdx.y * 32;
    int tx = threadIdx.x & 31, ty = threadIdx.x >> 5;
#pragma unroll
    for (int e = 0; e < 4; e++)
        ts[ty + 8*e][tx] = W[(size_t)(k0 + ty + 8*e)*C_ + n0 + tx];
    __syncthreads();
#pragma unroll
    for (int e = 0; e < 4; e++) {
        int n = ty + 8*e;
        float v = ts[tx][n];
        __nv_bfloat16 h = __float2bfloat16(v);
        Th[(size_t)(n0+n)*C_ + k0 + tx] = __bfloat16_as_ushort(h);
        Tl[(size_t)(n0+n)*C_ + k0 + tx] =
            __bfloat16_as_ushort(__float2bfloat16(v - __bfloat162float(h)));
    }
}

// ---------------- activation fp32 -> bf16 hi/lo split ----------------
__global__ void __launch_bounds__(256) asplit(
    const float* __restrict__ X, ushort_t* __restrict__ Hi, ushort_t* __restrict__ Lo)
{
    size_t i = ((size_t)blockIdx.x*256 + threadIdx.x) * 4;
    float4 v = *(const float4*)(X + i);
    uint2 h, l;
    cvt_split4(v, h, l);
    *(uint2*)(Hi + i) = h;
    *(uint2*)(Lo + i) = l;
}

// ---------------- bf16x3 HMMA GEMM: C[M,N] = A[M,K] @ B[K,N] ----------------
// A hi/lo [M,K] row-major bf16, B = W^T hi/lo [N,K] row-major bf16, C fp32.
// CTA 128(M) x 256(N), 512 threads (16 warps, 4x4 grid), warp tile 32x64,
// K-chunk 32, 3-stage cp.async pipe (prefetch-after-wait, round-4 schedule).
#define LDB     80            // padded row bytes (40 bf16): conflict-free ldmatrix
#define SZ_A    (128*LDB)     // 10240 per A buffer
#define SZ_B    (256*LDB)     // 20480 per B buffer
#define STAGE_B (2*SZ_A + 2*SZ_B)   // Ah, Al, Bh, Bl = 61440
#define NSTAGE  3
#define GEMM_SMEM (NSTAGE*STAGE_B)  // 184320

__device__ __forceinline__ void gemm_load_stage(
    uint32_t sb, int s, const ushort_t* Ah, const ushort_t* Al,
    const ushort_t* Bh, const ushort_t* Bl, int m0, int n0, int kt, int tid)
{
    int k0 = kt * 32;
    uint32_t base = sb + s*STAGE_B;
    // A: 128 rows x 4 chunks (hi+lo) — 512 threads, 1 chunk each
    {
        int row = tid >> 2, c = tid & 3;
        uint32_t d = base + row*LDB + c*16;
        size_t offA = (size_t)(m0 + row)*C_ + k0 + c*8;
        cp16(d,        Ah + offA);
        cp16(d + SZ_A, Al + offA);
    }
    // B: 256 rows x 4 chunks (hi+lo) — 2 chunks each
#pragma unroll
    for (int e = 0; e < 2; e++) {
        int q = tid + 512*e;
        int row = q >> 2, c = q & 3;
        uint32_t d = base + 2*SZ_A + row*LDB + c*16;
        size_t offB = (size_t)(n0 + row)*C_ + k0 + c*8;
        cp16(d,        Bh + offB);
        cp16(d + SZ_B, Bl + offB);
    }
    CP_COMMIT();
}

__global__ void __launch_bounds__(512, 1) gemm_bf3(
    const ushort_t* __restrict__ Ah, const ushort_t* __restrict__ Al,
    const ushort_t* __restrict__ Bh, const ushort_t* __restrict__ Bl,
    float* __restrict__ Cm)
{
    extern __shared__ char smem[];
    uint32_t sb = smem_u32(smem);
    int tid = threadIdx.x, lane = tid & 31, w = tid >> 5;
    int wm = w & 3, wn = w >> 2;           // 4 x 4 warp grid (M x N)
    int m0 = blockIdx.y * 128, n0 = blockIdx.x * 256;

    float acc[2][8][4];
#pragma unroll
    for (int i = 0; i < 2; i++)
#pragma unroll
        for (int j = 0; j < 8; j++)
#pragma unroll
            for (int q = 0; q < 4; q++) acc[i][j][q] = 0.f;

    gemm_load_stage(sb, 0, Ah, Al, Bh, Bl, m0, n0, 0, tid);
    gemm_load_stage(sb, 1, Ah, Al, Bh, Bl, m0, n0, 1, tid);

    // precomputed intra-warp ldmatrix offsets
    uint32_t a_off = (uint32_t)((wm*32 + (lane & 15))*LDB + (lane >> 4)*16);
    uint32_t b_off = (uint32_t)((wn*64 + (lane & 7) + ((lane >> 4) & 1)*8)*LDB
                                + ((lane >> 3) & 1)*16);

    for (int kt = 0; kt < C_/32; kt++) {
        int s = kt % NSTAGE;
        CP_WAIT1();
        __syncthreads();
        if (kt + 2 < C_/32)
            gemm_load_stage(sb, (kt+2) % NSTAGE, Ah, Al, Bh, Bl, m0, n0, kt+2, tid);

        uint32_t base = sb + s*STAGE_B;
#pragma unroll
        for (int kk = 0; kk < 2; kk++) {
            uint32_t ah[2][4], al[2][4], bh[4][4], bl[4][4];
#pragma unroll
            for (int mt = 0; mt < 2; mt++) {
                uint32_t addr = base + a_off + mt*16*LDB + kk*32;
                ldsm_x4(ah[mt], addr);
                ldsm_x4(al[mt], addr + SZ_A);
            }
#pragma unroll
            for (int g = 0; g < 4; g++) {
                uint32_t addr = base + 2*SZ_A + b_off + g*16*LDB + kk*32;
                ldsm_x4(bh[g], addr);
                ldsm_x4(bl[g], addr + SZ_B);
            }
#pragma unroll
            for (int mt = 0; mt < 2; mt++)
#pragma unroll
                for (int nt = 0; nt < 8; nt++) {
                    const uint32_t* bph = &bh[nt >> 1][(nt & 1)*2];
                    const uint32_t* bpl = &bl[nt >> 1][(nt & 1)*2];
                    mma16816(acc[mt][nt], ah[mt], bph);   // hh
                    mma16816(acc[mt][nt], ah[mt], bpl);   // h*lo
                    mma16816(acc[mt][nt], al[mt], bph);   // lo*h
                }
        }
    }

    // epilogue: direct fp32 stores
#pragma unroll
    for (int mt = 0; mt < 2; mt++) {
        int r0 = m0 + wm*32 + mt*16 + (lane >> 2);
#pragma unroll
        for (int nt = 0; nt < 8; nt++) {
            int c0 = n0 + wn*64 + nt*8 + (lane & 3)*2;
            *(float2*)&Cm[(size_t)r0*C_ + c0] =
                make_float2(acc[mt][nt][0], acc[mt][nt][1]);
            *(float2*)&Cm[(size_t)(r0+8)*C_ + c0] =
                make_float2(acc[mt][nt][2], acc[mt][nt][3]);
        }
    }
}

// ---------------- skinny GEMM + tanh ----------------
template<int NS, bool FUSE>
__global__ void __launch_bounds__(256) skinny_tanh_gemm(
    const float* __restrict__ A, const float* __restrict__ W,
    float* __restrict__ out,
    const float* __restrict__ shift, const float* __restrict__ maax)
{
    __shared__ float As[32*68];
    __shared__ float Ws[32*NS];
    const int tid = threadIdx.x;
    const int m0  = blockIdx.x * 64;
    const int row = tid >> 2;
    const int cg  = tid & 3;

    float acc[NS/4];
#pragma unroll
    for (int i = 0; i < NS/4; i++) acc[i] = 0.f;

    for (int k0 = 0; k0 < C_; k0 += 32) {
#pragma unroll
        for (int e = 0; e < 2; e++) {
            int q  = tid + 256*e;
            int r  = q >> 3;
            int c4 = (q & 7) * 4;
            int m  = m0 + r;
            float4 val;
            if (FUSE) {
                float4 xv = *(const float4*)(A + (size_t)m*C_ + k0 + c4);
                int t = m & (T_-1);
                int b = m >> 11;
                float4 xp = (t > 0) ? *(const float4*)(A + (size_t)(m-1)*C_ + k0 + c4)
                                    : *(const float4*)(shift + (size_t)b*C_ + k0 + c4);
                float4 mx = *(const float4*)(maax + k0 + c4);
                val.x = xv.x + (xp.x - xv.x)*mx.x;
                val.y = xv.y + (xp.y - xv.y)*mx.y;
                val.z = xv.z + (xp.z - xv.z)*mx.z;
                val.w = xv.w + (xp.w - xv.w)*mx.w;
            } else {
                val = *(const float4*)(A + (size_t)m*C_ + k0 + c4);
            }
            As[(c4+0)*68 + r] = val.x;
            As[(c4+1)*68 + r] = val.y;
            As[(c4+2)*68 + r] = val.z;
            As[(c4+3)*68 + r] = val.w;
        }
        {
            const float4* src = (const float4*)(W + (size_t)k0*NS);
            for (int q = tid; q < 32*NS/4; q += 256)
                ((float4*)Ws)[q] = src[q];
        }
        __syncthreads();
#pragma unroll 8
        for (int k = 0; k < 32; k++) {
            float a = As[k*68 + row];
            const float* wrow = Ws + k*NS + cg*(NS/4);
#pragma unroll
            for (int j = 0; j < NS/16; j++) {
                float4 w4 = *(const float4*)(wrow + j*4);
                acc[j*4+0] = fmaf(a, w4.x, acc[j*4+0]);
                acc[j*4+1] = fmaf(a, w4.y, acc[j*4+1]);
                acc[j*4+2] = fmaf(a, w4.z, acc[j*4+2]);
                acc[j*4+3] = fmaf(a, w4.w, acc[j*4+3]);
            }
        }
        __syncthreads();
    }
    float* orow = out + (size_t)(m0+row)*NS + cg*(NS/4);
#pragma unroll
    for (int i = 0; i < NS/4; i++) orow[i] = tanhf(acc[i]);
}

// ---------------- 5-way mix apply ----------------
__global__ void __launch_bounds__(256) mix_apply_f(
    const float* __restrict__ x, const float* __restrict__ shift,
    const float* __restrict__ tm, const float* __restrict__ w2,
    const float* __restrict__ maa, float* __restrict__ out, int f)
{
    __shared__ float tmf[32*32];
    __shared__ float w2f[32*64];
    int tid = threadIdx.x;
    int m0 = blockIdx.y * 32;
    int c0 = blockIdx.x * 64;
    {
        int r = tid >> 3, c4 = (tid & 7) * 4;
        *(float4*)&tmf[r*32 + c4] =
            *(const float4*)(tm + (size_t)(m0+r)*160 + f*32 + c4);
    }
#pragma unroll
    for (int e = 0; e < 2; e++) {
        int q = tid + 256*e;
        int d = q >> 4, c4 = (q & 15) * 4;
        *(float4*)&w2f[d*64 + c4] =
            *(const float4*)(w2 + (size_t)(f*32+d)*C_ + c0 + c4);
    }
    __syncthreads();
#pragma unroll
    for (int e = 0; e < 2; e++) {
        int p = tid + 256*e;
        int r  = p >> 4;
        int c4 = (p & 15) * 4;
        int m = m0 + r;
        int c = c0 + c4;
        float4 acc = make_float4(0.f,0.f,0.f,0.f);
#pragma unroll
        for (int d = 0; d < 32; d++) {
            float tv = tmf[r*32 + d];
            float4 w4 = *(const float4*)&w2f[d*64 + c4];
            acc.x = fmaf(tv, w4.x, acc.x);
            acc.y = fmaf(tv, w4.y, acc.y);
            acc.z = fmaf(tv, w4.z, acc.z);
            acc.w = fmaf(tv, w4.w, acc.w);
        }
        float4 xv = *(const float4*)(x + (size_t)m*C_ + c);
        int t = m & (T_-1), b = m >> 11;
        float4 xp = (t > 0) ? *(const float4*)(x + (size_t)(m-1)*C_ + c)
                            : *(const float4*)(shift + (size_t)b*C_ + c);
        float4 ma = *(const float4*)(maa + c);
        float4 o;
        o.x = xv.x + (xp.x - xv.x)*(ma.x + acc.x);
        o.y = xv.y + (xp.y - xv.y)*(ma.y + acc.y);
        o.z = xv.z + (xp.z - xv.z)*(ma.z + acc.z);
        o.w = xv.w + (xp.w - xv.w)*(ma.w + acc.w);
        *(float4*)(out + (size_t)m*C_ + c) = o;
    }
}

// ---------------- small-K GEMM (K=64) with fused epilogues ----------------
template<int MODE>
__global__ void __launch_bounds__(256) smallk_gemm(
    const float* __restrict__ A, const float* __restrict__ W,
    const float* __restrict__ td, float* __restrict__ out1,
    float* __restrict__ karr)
{
    __shared__ float As[32*64];
    __shared__ float Ws[64*128];
    int tid = threadIdx.x;
    int m0 = blockIdx.y * 32, c0 = blockIdx.x * 128;
    {
        const float4* src = (const float4*)(A + (size_t)m0*64);
#pragma unroll
        for (int q = tid; q < 512; q += 256) ((float4*)As)[q] = src[q];
    }
#pragma unroll
    for (int e = 0; e < 8; e++) {
        int q = tid + 256*e;
        int kr = q >> 5, c4 = (q & 31) * 4;
        *(float4*)&Ws[kr*128 + c4] = *(const float4*)(W + (size_t)kr*C_ + c0 + c4);
    }
    __syncthreads();
    int ty = tid >> 4, tx = tid & 15;
    int r0 = ty * 2;
    float acc[2][8];
#pragma unroll
    for (int i = 0; i < 2; i++)
#pragma unroll
        for (int j = 0; j < 8; j++) acc[i][j] = 0.f;
#pragma unroll
    for (int k = 0; k < 64; k++) {
        float a0 = As[r0*64 + k];
        float a1 = As[(r0+1)*64 + k];
        float4 b0 = *(const float4*)&Ws[k*128 + tx*8];
        float4 b1 = *(const float4*)&Ws[k*128 + tx*8 + 4];
        float bv[8] = {b0.x,b0.y,b0.z,b0.w,b1.x,b1.y,b1.z,b1.w};
#pragma unroll
        for (int j = 0; j < 8; j++) {
            acc[0][j] = fmaf(a0, bv[j], acc[0][j]);
            acc[1][j] = fmaf(a1, bv[j], acc[1][j]);
        }
    }
#pragma unroll
    for (int rr = 0; rr < 2; rr++) {
        int m = m0 + r0 + rr;
        size_t base = (size_t)m*C_ + c0 + tx*8;
        if (MODE == 0) {
#pragma unroll
            for (int j = 0; j < 8; j++) {
                float w = td[c0 + tx*8 + j] + acc[rr][j];
                float dd = expf(-expf(w));
                out1[base + j] = dd;
                karr[base + j] *= (1.0f - dd);
            }
        } else {
#pragma unroll
            for (int j = 0; j < 8; j++) out1[base + j] += acc[rr][j];
        }
    }
}

// ---------------- WKV scan ----------------
__global__ void __launch_bounds__(64) wkv_scan(
    const float* __restrict__ rp, const float* __restrict__ kp,
    const float* __restrict__ vp, const float* __restrict__ dp,
    const float* __restrict__ S0, float* __restrict__ yp,
    float* __restrict__ Sout)
{
    int bh = blockIdx.x;
    int j = threadIdx.x;
    int b = bh >> 5, h = bh & (H_-1);
    float S[64];
    const float* s0 = S0 + (size_t)bh*HS_*HS_ + j;
#pragma unroll
    for (int i = 0; i < 64; i++) S[i] = s0[(size_t)i*64];
    __shared__ float4 skd[64];
    size_t idx = (size_t)b*T_*C_ + (size_t)h*64 + j;
    float rr = rp[idx], kk = kp[idx], dd = dp[idx], vv = vp[idx];
    for (int t = 0; t < T_; t++) {
        float rn = 0.f, kn = 0.f, dn = 0.f, vn = 0.f;
        if (t + 1 < T_) {
            size_t nx = idx + C_;
            rn = rp[nx]; kn = kp[nx]; dn = dp[nx]; vn = vp[nx];
        }
        skd[j] = make_float4(rr, kk, dd, 0.f);
        __syncthreads();
        float acc = 0.f;
#pragma unroll
        for (int i = 0; i < 64; i++) {
            float4 q = skd[i];
            acc  = fmaf(q.x, S[i], acc);
            S[i] = fmaf(q.z, S[i], q.y * vv);
        }
        yp[idx] = acc;
        __syncthreads();
        idx += C_;
        rr = rn; kk = kn; dd = dn; vv = vn;
    }
    float* so = Sout + (size_t)bh*HS_*HS_ + j;
#pragma unroll
    for (int i = 0; i < 64; i++) so[(size_t)i*64] = S[i];
}

// ---------------- fused add + LayerNorm, emits bf16 hi/lo split ----------------
__global__ void __launch_bounds__(256) ln_add_split(
    const float* __restrict__ a, const float* __restrict__ b,
    const float* __restrict__ lw, const float* __restrict__ lb,
    ushort_t* __restrict__ oh, ushort_t* __restrict__ ol)
{
    int m = blockIdx.x;
    int tid = threadIdx.x;
    const float* ar = a + (size_t)m*C_;
    const float* br = b + (size_t)m*C_;
    float vals[8];
    float s = 0.f, s2 = 0.f;
#pragma unroll
    for (int i = 0; i < 8; i++) {
        int c = tid + 256*i;
        float u = ar[c] + br[c];
        vals[i] = u; s += u; s2 = fmaf(u, u, s2);
    }
#pragma unroll
    for (int o = 16; o > 0; o >>= 1) {
        s  += __shfl_xor_sync(0xffffffffu, s,  o);
        s2 += __shfl_xor_sync(0xffffffffu, s2, o);
    }
    __shared__ float sa[8], sb2[8];
    if ((tid & 31) == 0) { sa[tid>>5] = s; sb2[tid>>5] = s2; }
    __syncthreads();
    s = 0.f; s2 = 0.f;
#pragma unroll
    for (int i = 0; i < 8; i++) { s += sa[i]; s2 += sb2[i]; }
    float mu  = s * (1.0f/C_);
    float var = s2 * (1.0f/C_) - mu*mu;
    float inv = rsqrtf(var + 1e-5f);
#pragma unroll
    for (int i = 0; i < 8; i++) {
        int c = tid + 256*i;
        float v = (vals[i] - mu)*inv*lw[c] + lb[c];
        __nv_bfloat16 hb = __float2bfloat16(v);
        oh[(size_t)m*C_ + c] = __bfloat16_as_ushort(hb);
        ol[(size_t)m*C_ + c] =
            __bfloat16_as_ushort(__float2bfloat16(v - __bfloat162float(hb)));
    }
}

__global__ void copy_xlast(const float* __restrict__ x, float* __restrict__ o)
{
    int i = blockIdx.x*256 + threadIdx.x;
    int b = i >> 11, c = i & (C_-1);
    o[i] = x[((size_t)b*T_ + (T_-1))*C_ + c];
}

// ---------------- launcher ----------------
extern "C" void kernel_launch(void* const* d_in, const int* in_sizes, int n_in,
                              void* d_out, int out_size)
{
    (void)in_sizes; (void)n_in;
    const float* x     = (const float*)d_in[0];
    const float* shift = (const float*)d_in[1];
    const float* wkv0  = (const float*)d_in[2];
    const float* maax  = (const float*)d_in[3];
    const float* maar  = (const float*)d_in[4];
    const float* maak  = (const float*)d_in[5];
    const float* maav  = (const float*)d_in[6];
    const float* maaw  = (const float*)d_in[7];
    const float* maav2 = (const float*)d_in[8];
    const float* w1    = (const float*)d_in[9];
    const float* w2    = (const float*)d_in[10];
    const float* tdec  = (const float*)d_in[11];
    const float* dw1   = (const float*)d_in[12];
    const float* dw2   = (const float*)d_in[13];
    const float* vw1   = (const float*)d_in[14];
    const float* vw2   = (const float*)d_in[15];
    const float* Wr    = (const float*)d_in[17];
    const float* Wk    = (const float*)d_in[18];
    const float* Wv    = (const float*)d_in[19];
    const float* Wo    = (const float*)d_in[20];
    const float* lnw   = (const float*)d_in[21];
    const float* lnb   = (const float*)d_in[22];
    float* out = (float*)d_out;

    float *tm,*xr,*xk,*xv,*xw,*xv2,*rb,*kb,*vb,*v2b,*db,*lwv,*lv2,*yw;
    ushort_t *ah,*al,*wrh,*wrl,*wkh,*wkl,*wvh,*wvl,*woh,*wol;
    cudaGetSymbolAddress((void**)&tm,  g_tm);
    cudaGetSymbolAddress((void**)&xr,  g_xr);
    cudaGetSymbolAddress((void**)&xk,  g_xk);
    cudaGetSymbolAddress((void**)&xv,  g_xv);
    cudaGetSymbolAddress((void**)&xw,  g_xw);
    cudaGetSymbolAddress((void**)&xv2, g_xv2);
    cudaGetSymbolAddress((void**)&rb,  g_r);
    cudaGetSymbolAddress((void**)&kb,  g_k);
    cudaGetSymbolAddress((void**)&vb,  g_v);
    cudaGetSymbolAddress((void**)&v2b, g_v2);
    cudaGetSymbolAddress((void**)&db,  g_d);
    cudaGetSymbolAddress((void**)&lwv, g_lw);
    cudaGetSymbolAddress((void**)&lv2, g_lv2);
    cudaGetSymbolAddress((void**)&yw,  g_yw);
    cudaGetSymbolAddress((void**)&ah,  g_ah);
    cudaGetSymbolAddress((void**)&al,  g_al);
    cudaGetSymbolAddress((void**)&wrh, g_wrh);
    cudaGetSymbolAddress((void**)&wrl, g_wrl);
    cudaGetSymbolAddress((void**)&wkh, g_wkh);
    cudaGetSymbolAddress((void**)&wkl, g_wkl);
    cudaGetSymbolAddress((void**)&wvh, g_wvh);
    cudaGetSymbolAddress((void**)&wvl, g_wvl);
    cudaGetSymbolAddress((void**)&woh, g_woh);
    cudaGetSymbolAddress((void**)&wol, g_wol);

    cudaFuncSetAttribute(gemm_bf3, cudaFuncAttributeMaxDynamicSharedMemorySize, GEMM_SMEM);

    // 0) weight transpose + bf16 split
    {
        dim3 gt(C_/32, C_/32);
        wsplit_t<<<gt,256>>>(Wr, wrh, wrl);
        wsplit_t<<<gt,256>>>(Wk, wkh, wkl);
        wsplit_t<<<gt,256>>>(Wv, wvh, wvl);
        wsplit_t<<<gt,256>>>(Wo, woh, wol);
    }

    // 1) LoRA-5 projection with fused token-shift mixing
    skinny_tanh_gemm<160, true><<<M_/64, 256>>>(x, w1, tm, shift, maax);

    // 2) 5-way mix
    {
        dim3 g(C_/64, M_/32);
        mix_apply_f<<<g,256>>>(x, shift, tm, w2, maar,  xr,  0);
        mix_apply_f<<<g,256>>>(x, shift, tm, w2, maak,  xk,  1);
        mix_apply_f<<<g,256>>>(x, shift, tm, w2, maav,  xv,  2);
        mix_apply_f<<<g,256>>>(x, shift, tm, w2, maaw,  xw,  3);
        mix_apply_f<<<g,256>>>(x, shift, tm, w2, maav2, xv2, 4);
    }

    // 3) big projections via HMMA bf16x3 (split activation, then GEMM)
    const int NSPLIT = (int)(((size_t)M_*C_/4) / 256);
    dim3 gg(C_/256, M_/128);
    asplit<<<NSPLIT,256>>>(xr, ah, al);
    gemm_bf3<<<gg,512,GEMM_SMEM>>>(ah, al, wrh, wrl, rb);
    asplit<<<NSPLIT,256>>>(xk, ah, al);
    gemm_bf3<<<gg,512,GEMM_SMEM>>>(ah, al, wkh, wkl, kb);
    asplit<<<NSPLIT,256>>>(xv, ah, al);
    gemm_bf3<<<gg,512,GEMM_SMEM>>>(ah, al, wvh, wvl, vb);
    asplit<<<NSPLIT,256>>>(xv2, ah, al);
    gemm_bf3<<<gg,512,GEMM_SMEM>>>(ah, al, wvh, wvl, v2b);

    // 4) decay / value2 LoRAs
    skinny_tanh_gemm<64, false><<<M_/64, 256>>>(xw,  dw1, lwv, nullptr, nullptr);
    skinny_tanh_gemm<64, false><<<M_/64, 256>>>(xv2, vw1, lv2, nullptr, nullptr);
    {
        dim3 gs(C_/128, M_/32);
        smallk_gemm<0><<<gs,256>>>(lwv, dw2, tdec, db,  kb);
        smallk_gemm<1><<<gs,256>>>(lv2, vw2, nullptr, v2b, nullptr);
    }

    // 5) WKV scan, 6) add v2 + LayerNorm (split output), 7) output projection
    const size_t OFFS = (size_t)M_*C_;
    const size_t OFFX = OFFS + (size_t)B_*H_*HS_*HS_;
    bool full = (size_t)out_size >= OFFX + (size_t)B_*C_;
    float* Sout = full ? (out + OFFS) : tm;
    wkv_scan<<<B_*H_, 64>>>(rb, kb, vb, db, wkv0, yw, Sout);
    ln_add_split<<<M_, 256>>>(yw, v2b, lnw, lnb, ah, al);
    gemm_bf3<<<gg,512,GEMM_SMEM>>>(ah, al, woh, wol, out);
    if (full) copy_xlast<<<(B_*C_)/256, 256>>>(x, out + OFFX);
}

// round 10
// speedup vs baseline: 1.2463x; 1.0167x over previous
#include <cuda_runtime.h>
#include <cuda_bf16.h>
#include <math.h>
#include <stdint.h>

#define B_ 8
#define T_ 2048
#define C_ 2048
#define H_ 32
#define HS_ 64
#define M_ (B_*T_)   // 16384

typedef unsigned short ushort_t;

// ---------------- scratch (__device__ globals: allocation-free) ----------------
__device__ float g_tm [(size_t)M_*160];
__device__ float g_xr [(size_t)M_*C_];   // holds bf16 hi/lo split of xr
__device__ float g_xk [(size_t)M_*C_];   // holds bf16 hi/lo split of xk
__device__ float g_xv [(size_t)M_*C_];   // holds bf16 hi/lo split of xv
__device__ float g_xw [(size_t)M_*C_];
__device__ float g_xv2[(size_t)M_*C_];
__device__ float g_r  [(size_t)M_*C_];
__device__ float g_k  [(size_t)M_*C_];
__device__ float g_v  [(size_t)M_*C_];
__device__ float g_v2 [(size_t)M_*C_];
__device__ float g_d  [(size_t)M_*C_];
__device__ float g_lw [(size_t)M_*64];
__device__ float g_lv2[(size_t)M_*64];
__device__ float g_yw [(size_t)M_*C_];

// bf16 hi/lo split scratch (xv2 split, later yln split)
__device__ ushort_t g_ah[(size_t)M_*C_];
__device__ ushort_t g_al[(size_t)M_*C_];

// transposed + split weights: [N, K] bf16 hi/lo
__device__ ushort_t g_wrh[(size_t)C_*C_];
__device__ ushort_t g_wrl[(size_t)C_*C_];
__device__ ushort_t g_wkh[(size_t)C_*C_];
__device__ ushort_t g_wkl[(size_t)C_*C_];
__device__ ushort_t g_wvh[(size_t)C_*C_];
__device__ ushort_t g_wvl[(size_t)C_*C_];
__device__ ushort_t g_woh[(size_t)C_*C_];
__device__ ushort_t g_wol[(size_t)C_*C_];

// ================= low-level helpers (base-target PTX only) =================
__device__ __forceinline__ uint32_t smem_u32(const void* p) {
    uint32_t a;
    asm("{ .reg .u64 t; cvta.to.shared.u64 t, %1; cvt.u32.u64 %0, t; }" : "=r"(a) : "l"(p));
    return a;
}
__device__ __forceinline__ void cp16(uint32_t dst, const void* src) {
    asm volatile("cp.async.cg.shared.global [%0], [%1], 16;" :: "r"(dst), "l"(src) : "memory");
}
#define CP_COMMIT() asm volatile("cp.async.commit_group;" ::: "memory")
#define CP_WAIT1()  asm volatile("cp.async.wait_group 1;"  ::: "memory")

__device__ __forceinline__ void ldsm_x4(uint32_t* r, uint32_t a) {
    asm volatile("ldmatrix.sync.aligned.m8n8.x4.shared.b16 {%0,%1,%2,%3}, [%4];"
        : "=r"(r[0]), "=r"(r[1]), "=r"(r[2]), "=r"(r[3]) : "r"(a));
}
__device__ __forceinline__ void mma16816(float* c, const uint32_t* a, const uint32_t* b) {
    asm volatile("mma.sync.aligned.m16n8k16.row.col.f32.bf16.bf16.f32 "
        "{%0,%1,%2,%3}, {%4,%5,%6,%7}, {%8,%9}, {%0,%1,%2,%3};"
        : "+f"(c[0]), "+f"(c[1]), "+f"(c[2]), "+f"(c[3])
        : "r"(a[0]), "r"(a[1]), "r"(a[2]), "r"(a[3]), "r"(b[0]), "r"(b[1]));
}

__device__ __forceinline__ void split1(float v, ushort_t& h, ushort_t& l) {
    __nv_bfloat16 hb = __float2bfloat16(v);
    h = __bfloat16_as_ushort(hb);
    l = __bfloat16_as_ushort(__float2bfloat16(v - __bfloat162float(hb)));
}

// ---------------- weight transpose + bf16 hi/lo split: T[n][k] = W[k][n] ----------------
__global__ void __launch_bounds__(256) wsplit_t(
    const float* __restrict__ W,
    ushort_t* __restrict__ Th, ushort_t* __restrict__ Tl)
{
    __shared__ float ts[32][33];
    int n0 = blockIdx.x * 32, k0 = blockIdx.y * 32;
    int tx = threadIdx.x & 31, ty = threadIdx.x >> 5;
#pragma unroll
    for (int e = 0; e < 4; e++)
        ts[ty + 8*e][tx] = W[(size_t)(k0 + ty + 8*e)*C_ + n0 + tx];
    __syncthreads();
#pragma unroll
    for (int e = 0; e < 4; e++) {
        int n = ty + 8*e;
        float v = ts[tx][n];
        ushort_t h, l;
        split1(v, h, l);
        Th[(size_t)(n0+n)*C_ + k0 + tx] = h;
        Tl[(size_t)(n0+n)*C_ + k0 + tx] = l;
    }
}

// ---------------- bf16x3 HMMA GEMM: C[M,N] = A[M,K] @ B[K,N] ----------------
// CTA 128(M) x 256(N), 512 threads (16 warps, 4x4 grid), warp tile 32x64,
// K-chunk 32, 3-stage cp.async pipe (prefetch-after-wait schedule).
#define LDB     80            // padded row bytes (40 bf16): conflict-free ldmatrix
#define SZ_A    (128*LDB)     // 10240 per A buffer
#define SZ_B    (256*LDB)     // 20480 per B buffer
#define STAGE_B (2*SZ_A + 2*SZ_B)   // Ah, Al, Bh, Bl = 61440
#define NSTAGE  3
#define GEMM_SMEM (NSTAGE*STAGE_B)  // 184320

__device__ __forceinline__ void gemm_load_stage(
    uint32_t sb, int s, const ushort_t* Ah, const ushort_t* Al,
    const ushort_t* Bh, const ushort_t* Bl, int m0, int n0, int kt, int tid)
{
    int k0 = kt * 32;
    uint32_t base = sb + s*STAGE_B;
    {
        int row = tid >> 2, c = tid & 3;
        uint32_t d = base + row*LDB + c*16;
        size_t offA = (size_t)(m0 + row)*C_ + k0 + c*8;
        cp16(d,        Ah + offA);
        cp16(d + SZ_A, Al + offA);
    }
#pragma unroll
    for (int e = 0; e < 2; e++) {
        int q = tid + 512*e;
        int row = q >> 2, c = q & 3;
        uint32_t d = base + 2*SZ_A + row*LDB + c*16;
        size_t offB = (size_t)(n0 + row)*C_ + k0 + c*8;
        cp16(d,        Bh + offB);
        cp16(d + SZ_B, Bl + offB);
    }
    CP_COMMIT();
}

__global__ void __launch_bounds__(512, 1) gemm_bf3(
    const ushort_t* __restrict__ Ah, const ushort_t* __restrict__ Al,
    const ushort_t* __restrict__ Bh, const ushort_t* __restrict__ Bl,
    float* __restrict__ Cm)
{
    extern __shared__ char smem[];
    uint32_t sb = smem_u32(smem);
    int tid = threadIdx.x, lane = tid & 31, w = tid >> 5;
    int wm = w & 3, wn = w >> 2;           // 4 x 4 warp grid (M x N)
    int m0 = blockIdx.y * 128, n0 = blockIdx.x * 256;

    float acc[2][8][4];
#pragma unroll
    for (int i = 0; i < 2; i++)
#pragma unroll
        for (int j = 0; j < 8; j++)
#pragma unroll
            for (int q = 0; q < 4; q++) acc[i][j][q] = 0.f;

    gemm_load_stage(sb, 0, Ah, Al, Bh, Bl, m0, n0, 0, tid);
    gemm_load_stage(sb, 1, Ah, Al, Bh, Bl, m0, n0, 1, tid);

    uint32_t a_off = (uint32_t)((wm*32 + (lane & 15))*LDB + (lane >> 4)*16);
    uint32_t b_off = (uint32_t)((wn*64 + (lane & 7) + ((lane >> 4) & 1)*8)*LDB
                                + ((lane >> 3) & 1)*16);

    for (int kt = 0; kt < C_/32; kt++) {
        int s = kt % NSTAGE;
        CP_WAIT1();
        __syncthreads();
        if (kt + 2 < C_/32)
            gemm_load_stage(sb, (kt+2) % NSTAGE, Ah, Al, Bh, Bl, m0, n0, kt+2, tid);

        uint32_t base = sb + s*STAGE_B;
#pragma unroll
        for (int kk = 0; kk < 2; kk++) {
            uint32_t ah[2][4], al[2][4], bh[4][4], bl[4][4];
#pragma unroll
            for (int mt = 0; mt < 2; mt++) {
                uint32_t addr = base + a_off + mt*16*LDB + kk*32;
                ldsm_x4(ah[mt], addr);
                ldsm_x4(al[mt], addr + SZ_A);
            }
#pragma unroll
            for (int g = 0; g < 4; g++) {
                uint32_t addr = base + 2*SZ_A + b_off + g*16*LDB + kk*32;
                ldsm_x4(bh[g], addr);
                ldsm_x4(bl[g], addr + SZ_B);
            }
#pragma unroll
            for (int mt = 0; mt < 2; mt++)
#pragma unroll
                for (int nt = 0; nt < 8; nt++) {
                    const uint32_t* bph = &bh[nt >> 1][(nt & 1)*2];
                    const uint32_t* bpl = &bl[nt >> 1][(nt & 1)*2];
                    mma16816(acc[mt][nt], ah[mt], bph);   // hh
                    mma16816(acc[mt][nt], ah[mt], bpl);   // h*lo
                    mma16816(acc[mt][nt], al[mt], bph);   // lo*h
                }
        }
    }

#pragma unroll
    for (int mt = 0; mt < 2; mt++) {
        int r0 = m0 + wm*32 + mt*16 + (lane >> 2);
#pragma unroll
        for (int nt = 0; nt < 8; nt++) {
            int c0 = n0 + wn*64 + nt*8 + (lane & 3)*2;
            *(float2*)&Cm[(size_t)r0*C_ + c0] =
                make_float2(acc[mt][nt][0], acc[mt][nt][1]);
            *(float2*)&Cm[(size_t)(r0+8)*C_ + c0] =
                make_float2(acc[mt][nt][2], acc[mt][nt][3]);
        }
    }
}

// ---------------- skinny GEMM + tanh ----------------
template<int NS, bool FUSE>
__global__ void __launch_bounds__(256) skinny_tanh_gemm(
    const float* __restrict__ A, const float* __restrict__ W,
    float* __restrict__ out,
    const float* __restrict__ shift, const float* __restrict__ maax)
{
    __shared__ float As[32*68];
    __shared__ float Ws[32*NS];
    const int tid = threadIdx.x;
    const int m0  = blockIdx.x * 64;
    const int row = tid >> 2;
    const int cg  = tid & 3;

    float acc[NS/4];
#pragma unroll
    for (int i = 0; i < NS/4; i++) acc[i] = 0.f;

    for (int k0 = 0; k0 < C_; k0 += 32) {
#pragma unroll
        for (int e = 0; e < 2; e++) {
            int q  = tid + 256*e;
            int r  = q >> 3;
            int c4 = (q & 7) * 4;
            int m  = m0 + r;
            float4 val;
            if (FUSE) {
                float4 xv = *(const float4*)(A + (size_t)m*C_ + k0 + c4);
                int t = m & (T_-1);
                int b = m >> 11;
                float4 xp = (t > 0) ? *(const float4*)(A + (size_t)(m-1)*C_ + k0 + c4)
                                    : *(const float4*)(shift + (size_t)b*C_ + k0 + c4);
                float4 mx = *(const float4*)(maax + k0 + c4);
                val.x = xv.x + (xp.x - xv.x)*mx.x;
                val.y = xv.y + (xp.y - xv.y)*mx.y;
                val.z = xv.z + (xp.z - xv.z)*mx.z;
                val.w = xv.w + (xp.w - xv.w)*mx.w;
            } else {
                val = *(const float4*)(A + (size_t)m*C_ + k0 + c4);
            }
            As[(c4+0)*68 + r] = val.x;
            As[(c4+1)*68 + r] = val.y;
            As[(c4+2)*68 + r] = val.z;
            As[(c4+3)*68 + r] = val.w;
        }
        {
            const float4* src = (const float4*)(W + (size_t)k0*NS);
            for (int q = tid; q < 32*NS/4; q += 256)
                ((float4*)Ws)[q] = src[q];
        }
        __syncthreads();
#pragma unroll 8
        for (int k = 0; k < 32; k++) {
            float a = As[k*68 + row];
            const float* wrow = Ws + k*NS + cg*(NS/4);
#pragma unroll
            for (int j = 0; j < NS/16; j++) {
                float4 w4 = *(const float4*)(wrow + j*4);
                acc[j*4+0] = fmaf(a, w4.x, acc[j*4+0]);
                acc[j*4+1] = fmaf(a, w4.y, acc[j*4+1]);
                acc[j*4+2] = fmaf(a, w4.z, acc[j*4+2]);
                acc[j*4+3] = fmaf(a, w4.w, acc[j*4+3]);
            }
        }
        __syncthreads();
    }
    float* orow = out + (size_t)(m0+row)*NS + cg*(NS/4);
#pragma unroll
    for (int i = 0; i < NS/4; i++) orow[i] = tanhf(acc[i]);
}

// ---------------- 5-way mix apply, per-f, templated output mode ----------------
// MODE 0: bf16 hi/lo split only.  MODE 1: fp32 only.  MODE 2: fp32 + split.
template<int MODE>
__global__ void __launch_bounds__(256) mix_apply_f(
    const float* __restrict__ x, const float* __restrict__ shift,
    const float* __restrict__ tm, const float* __restrict__ w2,
    const float* __restrict__ maa,
    ushort_t* __restrict__ oh, ushort_t* __restrict__ ol,
    float* __restrict__ of, int f)
{
    __shared__ float tmf[32*32];
    __shared__ float w2f[32*64];
    int tid = threadIdx.x;
    int m0 = blockIdx.y * 32;
    int c0 = blockIdx.x * 64;
    {
        int r = tid >> 3, c4 = (tid & 7) * 4;
        *(float4*)&tmf[r*32 + c4] =
            *(const float4*)(tm + (size_t)(m0+r)*160 + f*32 + c4);
    }
#pragma unroll
    for (int e = 0; e < 2; e++) {
        int q = tid + 256*e;
        int d = q >> 4, c4 = (q & 15) * 4;
        *(float4*)&w2f[d*64 + c4] =
            *(const float4*)(w2 + (size_t)(f*32+d)*C_ + c0 + c4);
    }
    __syncthreads();
#pragma unroll
    for (int e = 0; e < 2; e++) {
        int p = tid + 256*e;
        int r  = p >> 4;
        int c4 = (p & 15) * 4;
        int m = m0 + r;
        int c = c0 + c4;
        float4 acc = make_float4(0.f,0.f,0.f,0.f);
#pragma unroll
        for (int d = 0; d < 32; d++) {
            float tv = tmf[r*32 + d];
            float4 w4 = *(const float4*)&w2f[d*64 + c4];
            acc.x = fmaf(tv, w4.x, acc.x);
            acc.y = fmaf(tv, w4.y, acc.y);
            acc.z = fmaf(tv, w4.z, acc.z);
            acc.w = fmaf(tv, w4.w, acc.w);
        }
        float4 xv = *(const float4*)(x + (size_t)m*C_ + c);
        int t = m & (T_-1), b = m >> 11;
        float4 xp = (t > 0) ? *(const float4*)(x + (size_t)(m-1)*C_ + c)
                            : *(const float4*)(shift + (size_t)b*C_ + c);
        float4 ma = *(const float4*)(maa + c);
        float4 o;
        o.x = xv.x + (xp.x - xv.x)*(ma.x + acc.x);
        o.y = xv.y + (xp.y - xv.y)*(ma.y + acc.y);
        o.z = xv.z + (xp.z - xv.z)*(ma.z + acc.z);
        o.w = xv.w + (xp.w - xv.w)*(ma.w + acc.w);
        size_t base = (size_t)m*C_ + c;
        if (MODE == 1 || MODE == 2)
            *(float4*)(of + base) = o;
        if (MODE == 0 || MODE == 2) {
            ushort4 h4, l4;
            split1(o.x, h4.x, l4.x);
            split1(o.y, h4.y, l4.y);
            split1(o.z, h4.z, l4.z);
            split1(o.w, h4.w, l4.w);
            *(ushort4*)(oh + base) = h4;
            *(ushort4*)(ol + base) = l4;
        }
    }
}

// ---------------- small-K GEMM (K=64) with fused epilogues ----------------
template<int MODE>
__global__ void __launch_bounds__(256) smallk_gemm(
    const float* __restrict__ A, const float* __restrict__ W,
    const float* __restrict__ td, float* __restrict__ out1,
    float* __restrict__ karr)
{
    __shared__ float As[32*64];
    __shared__ float Ws[64*128];
    int tid = threadIdx.x;
    int m0 = blockIdx.y * 32, c0 = blockIdx.x * 128;
    {
        const float4* src = (const float4*)(A + (size_t)m0*64);
#pragma unroll
        for (int q = tid; q < 512; q += 256) ((float4*)As)[q] = src[q];
    }
#pragma unroll
    for (int e = 0; e < 8; e++) {
        int q = tid + 256*e;
        int kr = q >> 5, c4 = (q & 31) * 4;
        *(float4*)&Ws[kr*128 + c4] = *(const float4*)(W + (size_t)kr*C_ + c0 + c4);
    }
    __syncthreads();
    int ty = tid >> 4, tx = tid & 15;
    int r0 = ty * 2;
    float acc[2][8];
#pragma unroll
    for (int i = 0; i < 2; i++)
#pragma unroll
        for (int j = 0; j < 8; j++) acc[i][j] = 0.f;
#pragma unroll
    for (int k = 0; k < 64; k++) {
        float a0 = As[r0*64 + k];
        float a1 = As[(r0+1)*64 + k];
        float4 b0 = *(const float4*)&Ws[k*128 + tx*8];
        float4 b1 = *(const float4*)&Ws[k*128 + tx*8 + 4];
        float bv[8] = {b0.x,b0.y,b0.z,b0.w,b1.x,b1.y,b1.z,b1.w};
#pragma unroll
        for (int j = 0; j < 8; j++) {
            acc[0][j] = fmaf(a0, bv[j], acc[0][j]);
            acc[1][j] = fmaf(a1, bv[j], acc[1][j]);
        }
    }
#pragma unroll
    for (int rr = 0; rr < 2; rr++) {
        int m = m0 + r0 + rr;
        size_t base = (size_t)m*C_ + c0 + tx*8;
        if (MODE == 0) {
#pragma unroll
            for (int j = 0; j < 8; j++) {
                float w = td[c0 + tx*8 + j] + acc[rr][j];
                float dd = expf(-expf(w));
                out1[base + j] = dd;
                karr[base + j] *= (1.0f - dd);
            }
        } else {
#pragma unroll
            for (int j = 0; j < 8; j++) out1[base + j] += acc[rr][j];
        }
    }
}

// ---------------- WKV scan ----------------
__global__ void __launch_bounds__(64) wkv_scan(
    const float* __restrict__ rp, const float* __restrict__ kp,
    const float* __restrict__ vp, const float* __restrict__ dp,
    const float* __restrict__ S0, float* __restrict__ yp,
    float* __restrict__ Sout)
{
    int bh = blockIdx.x;
    int j = threadIdx.x;
    int b = bh >> 5, h = bh & (H_-1);
    float S[64];
    const float* s0 = S0 + (size_t)bh*HS_*HS_ + j;
#pragma unroll
    for (int i = 0; i < 64; i++) S[i] = s0[(size_t)i*64];
    __shared__ float4 skd[64];
    size_t idx = (size_t)b*T_*C_ + (size_t)h*64 + j;
    float rr = rp[idx], kk = kp[idx], dd = dp[idx], vv = vp[idx];
    for (int t = 0; t < T_; t++) {
        float rn = 0.f, kn = 0.f, dn = 0.f, vn = 0.f;
        if (t + 1 < T_) {
            size_t nx = idx + C_;
            rn = rp[nx]; kn = kp[nx]; dn = dp[nx]; vn = vp[nx];
        }
        skd[j] = make_float4(rr, kk, dd, 0.f);
        __syncthreads();
        float acc = 0.f;
#pragma unroll
        for (int i = 0; i < 64; i++) {
            float4 q = skd[i];
            acc  = fmaf(q.x, S[i], acc);
            S[i] = fmaf(q.z, S[i], q.y * vv);
        }
        yp[idx] = acc;
        __syncthreads();
        idx += C_;
        rr = rn; kk = kn; dd = dn; vv = vn;
    }
    float* so = Sout + (size_t)bh*HS_*HS_ + j;
#pragma unroll
    for (int i = 0; i < 64; i++) so[(size_t)i*64] = S[i];
}

// ---------------- fused add + LayerNorm, emits bf16 hi/lo split ----------------
__global__ void __launch_bounds__(256) ln_add_split(
    const float* __restrict__ a, const float* __restrict__ b,
    const float* __restrict__ lw, const float* __restrict__ lb,
    ushort_t* __restrict__ oh, ushort_t* __restrict__ ol)
{
    int m = blockIdx.x;
    int tid = threadIdx.x;
    const float* ar = a + (size_t)m*C_;
    const float* br = b + (size_t)m*C_;
    float vals[8];
    float s = 0.f, s2 = 0.f;
#pragma unroll
    for (int i = 0; i < 8; i++) {
        int c = tid + 256*i;
        float u = ar[c] + br[c];
        vals[i] = u; s += u; s2 = fmaf(u, u, s2);
    }
#pragma unroll
    for (int o = 16; o > 0; o >>= 1) {
        s  += __shfl_xor_sync(0xffffffffu, s,  o);
        s2 += __shfl_xor_sync(0xffffffffu, s2, o);
    }
    __shared__ float sa[8], sb2[8];
    if ((tid & 31) == 0) { sa[tid>>5] = s; sb2[tid>>5] = s2; }
    __syncthreads();
    s = 0.f; s2 = 0.f;
#pragma unroll
    for (int i = 0; i < 8; i++) { s += sa[i]; s2 += sb2[i]; }
    float mu  = s * (1.0f/C_);
    float var = s2 * (1.0f/C_) - mu*mu;
    float inv = rsqrtf(var + 1e-5f);
#pragma unroll
    for (int i = 0; i < 8; i++) {
        int c = tid + 256*i;
        float v = (vals[i] - mu)*inv*lw[c] + lb[c];
        ushort_t h, l;
        split1(v, h, l);
        oh[(size_t)m*C_ + c] = h;
        ol[(size_t)m*C_ + c] = l;
    }
}

__global__ void copy_xlast(const float* __restrict__ x, float* __restrict__ o)
{
    int i = blockIdx.x*256 + threadIdx.x;
    int b = i >> 11, c = i & (C_-1);
    o[i] = x[((size_t)b*T_ + (T_-1))*C_ + c];
}

// ---------------- launcher ----------------
extern "C" void kernel_launch(void* const* d_in, const int* in_sizes, int n_in,
                              void* d_out, int out_size)
{
    (void)in_sizes; (void)n_in;
    const float* x     = (const float*)d_in[0];
    const float* shift = (const float*)d_in[1];
    const float* wkv0  = (const float*)d_in[2];
    const float* maax  = (const float*)d_in[3];
    const float* maar  = (const float*)d_in[4];
    const float* maak  = (const float*)d_in[5];
    const float* maav  = (const float*)d_in[6];
    const float* maaw  = (const float*)d_in[7];
    const float* maav2 = (const float*)d_in[8];
    const float* w1    = (const float*)d_in[9];
    const float* w2    = (const float*)d_in[10];
    const float* tdec  = (const float*)d_in[11];
    const float* dw1   = (const float*)d_in[12];
    const float* dw2   = (const float*)d_in[13];
    const float* vw1   = (const float*)d_in[14];
    const float* vw2   = (const float*)d_in[15];
    const float* Wr    = (const float*)d_in[17];
    const float* Wk    = (const float*)d_in[18];
    const float* Wv    = (const float*)d_in[19];
    const float* Wo    = (const float*)d_in[20];
    const float* lnw   = (const float*)d_in[21];
    const float* lnb   = (const float*)d_in[22];
    float* out = (float*)d_out;

    float *tm,*xrf,*xkf,*xvf,*xw,*xv2,*rb,*kb,*vb,*v2b,*db,*lwv,*lv2,*yw;
    ushort_t *ah,*al,*wrh,*wrl,*wkh,*wkl,*wvh,*wvl,*woh,*wol;
    cudaGetSymbolAddress((void**)&tm,  g_tm);
    cudaGetSymbolAddress((void**)&xrf, g_xr);
    cudaGetSymbolAddress((void**)&xkf, g_xk);
    cudaGetSymbolAddress((void**)&xvf, g_xv);
    cudaGetSymbolAddress((void**)&xw,  g_xw);
    cudaGetSymbolAddress((void**)&xv2, g_xv2);
    cudaGetSymbolAddress((void**)&rb,  g_r);
    cudaGetSymbolAddress((void**)&kb,  g_k);
    cudaGetSymbolAddress((void**)&vb,  g_v);
    cudaGetSymbolAddress((void**)&v2b, g_v2);
    cudaGetSymbolAddress((void**)&db,  g_d);
    cudaGetSymbolAddress((void**)&lwv, g_lw);
    cudaGetSymbolAddress((void**)&lv2, g_lv2);
    cudaGetSymbolAddress((void**)&yw,  g_yw);
    cudaGetSymbolAddress((void**)&ah,  g_ah);
    cudaGetSymbolAddress((void**)&al,  g_al);
    cudaGetSymbolAddress((void**)&wrh, g_wrh);
    cudaGetSymbolAddress((void**)&wrl, g_wrl);
    cudaGetSymbolAddress((void**)&wkh, g_wkh);
    cudaGetSymbolAddress((void**)&wkl, g_wkl);
    cudaGetSymbolAddress((void**)&wvh, g_wvh);
    cudaGetSymbolAddress((void**)&wvl, g_wvl);
    cudaGetSymbolAddress((void**)&woh, g_woh);
    cudaGetSymbolAddress((void**)&wol, g_wol);

    // xr/xk/xv fp32 buffers reinterpreted as bf16 hi/lo pairs
    ushort_t* xrh = (ushort_t*)xrf; ushort_t* xrl = xrh + (size_t)M_*C_;
    ushort_t* xkh = (ushort_t*)xkf; ushort_t* xkl = xkh + (size_t)M_*C_;
    ushort_t* xvh = (ushort_t*)xvf; ushort_t* xvl = xvh + (size_t)M_*C_;

    cudaFuncSetAttribute(gemm_bf3, cudaFuncAttributeMaxDynamicSharedMemorySize, GEMM_SMEM);

    // 0) weight transpose + bf16 split
    {
        dim3 gt(C_/32, C_/32);
        wsplit_t<<<gt,256>>>(Wr, wrh, wrl);
        wsplit_t<<<gt,256>>>(Wk, wkh, wkl);
        wsplit_t<<<gt,256>>>(Wv, wvh, wvl);
        wsplit_t<<<gt,256>>>(Wo, woh, wol);
    }

    // 1) LoRA-5 projection with fused token-shift mixing
    skinny_tanh_gemm<160, true><<<M_/64, 256>>>(x, w1, tm, shift, maax);

    // 2) 5-way mix (split emitted in-kernel; no asplit pass)
    {
        dim3 g(C_/64, M_/32);
        mix_apply_f<0><<<g,256>>>(x, shift, tm, w2, maar,  xrh, xrl, nullptr, 0);
        mix_apply_f<0><<<g,256>>>(x, shift, tm, w2, maak,  xkh, xkl, nullptr, 1);
        mix_apply_f<0><<<g,256>>>(x, shift, tm, w2, maav,  xvh, xvl, nullptr, 2);
        mix_apply_f<1><<<g,256>>>(x, shift, tm, w2, maaw,  nullptr, nullptr, xw, 3);
        mix_apply_f<2><<<g,256>>>(x, shift, tm, w2, maav2, ah, al, xv2, 4);
    }

    // 3) big projections via HMMA bf16x3
    dim3 gg(C_/256, M_/128);
    gemm_bf3<<<gg,512,GEMM_SMEM>>>(xrh, xrl, wrh, wrl, rb);
    gemm_bf3<<<gg,512,GEMM_SMEM>>>(xkh, xkl, wkh, wkl, kb);
    gemm_bf3<<<gg,512,GEMM_SMEM>>>(xvh, xvl, wvh, wvl, vb);
    gemm_bf3<<<gg,512,GEMM_SMEM>>>(ah,  al,  wvh, wvl, v2b);

    // 4) decay / value2 LoRAs
    skinny_tanh_gemm<64, false><<<M_/64, 256>>>(xw,  dw1, lwv, nullptr, nullptr);
    skinny_tanh_gemm<64, false><<<M_/64, 256>>>(xv2, vw1, lv2, nullptr, nullptr);
    {
        dim3 gs(C_/128, M_/32);
        smallk_gemm<0><<<gs,256>>>(lwv, dw2, tdec, db,  kb);
        smallk_gemm<1><<<gs,256>>>(lv2, vw2, nullptr, v2b, nullptr);
    }

    // 5) WKV scan, 6) add v2 + LayerNorm (split output), 7) output projection
    const size_t OFFS = (size_t)M_*C_;
    const size_t OFFX = OFFS + (size_t)B_*H_*HS_*HS_;
    bool full = (size_t)out_size >= OFFX + (size_t)B_*C_;
    float* Sout = full ? (out + OFFS) : tm;
    wkv_scan<<<B_*H_, 64>>>(rb, kb, vb, db, wkv0, yw, Sout);
    ln_add_split<<<M_, 256>>>(yw, v2b, lnw, lnb, ah, al);
    gemm_bf3<<<gg,512,GEMM_SMEM>>>(ah, al, woh, wol, out);
    if (full) copy_xlast<<<(B_*C_)/256, 256>>>(x, out + OFFX);
}

// round 11
// speedup vs baseline: 1.2783x; 1.0257x over previous
#include <cuda_runtime.h>
#include <cuda_bf16.h>
#include <math.h>
#include <stdint.h>

#define B_ 8
#define T_ 2048
#define C_ 2048
#define H_ 32
#define HS_ 64
#define M_ (B_*T_)   // 16384

typedef unsigned short ushort_t;

// ---------------- scratch (__device__ globals: allocation-free) ----------------
__device__ float g_tm [(size_t)M_*160];
__device__ float g_xr [(size_t)M_*C_];   // holds bf16 hi/lo split of xr
__device__ float g_xk [(size_t)M_*C_];   // holds bf16 hi/lo split of xk
__device__ float g_xv [(size_t)M_*C_];   // holds bf16 hi/lo split of xv
__device__ float g_xw [(size_t)M_*C_];
__device__ float g_xv2[(size_t)M_*C_];
__device__ float g_r  [(size_t)M_*C_];
__device__ float g_k  [(size_t)M_*C_];
__device__ float g_v  [(size_t)M_*C_];
__device__ float g_v2 [(size_t)M_*C_];
__device__ float g_d  [(size_t)M_*C_];
__device__ float g_lw [(size_t)M_*64];
__device__ float g_lv2[(size_t)M_*64];
__device__ float g_yw [(size_t)M_*C_];

// bf16 hi/lo split scratch (xv2 split, later yln split)
__device__ ushort_t g_ah[(size_t)M_*C_];
__device__ ushort_t g_al[(size_t)M_*C_];

// transposed + split weights: [N, K] bf16 hi/lo
__device__ ushort_t g_wrh[(size_t)C_*C_];
__device__ ushort_t g_wrl[(size_t)C_*C_];
__device__ ushort_t g_wkh[(size_t)C_*C_];
__device__ ushort_t g_wkl[(size_t)C_*C_];
__device__ ushort_t g_wvh[(size_t)C_*C_];
__device__ ushort_t g_wvl[(size_t)C_*C_];
__device__ ushort_t g_woh[(size_t)C_*C_];
__device__ ushort_t g_wol[(size_t)C_*C_];

// ================= low-level helpers (base-target PTX only) =================
__device__ __forceinline__ uint32_t smem_u32(const void* p) {
    uint32_t a;
    asm("{ .reg .u64 t; cvta.to.shared.u64 t, %1; cvt.u32.u64 %0, t; }" : "=r"(a) : "l"(p));
    return a;
}
__device__ __forceinline__ void cp16(uint32_t dst, const void* src) {
    asm volatile("cp.async.cg.shared.global [%0], [%1], 16;" :: "r"(dst), "l"(src) : "memory");
}
#define CP_COMMIT() asm volatile("cp.async.commit_group;" ::: "memory")
#define CP_WAIT1()  asm volatile("cp.async.wait_group 1;"  ::: "memory")

__device__ __forceinline__ void ldsm_x4(uint32_t* r, uint32_t a) {
    asm volatile("ldmatrix.sync.aligned.m8n8.x4.shared.b16 {%0,%1,%2,%3}, [%4];"
        : "=r"(r[0]), "=r"(r[1]), "=r"(r[2]), "=r"(r[3]) : "r"(a));
}
__device__ __forceinline__ void mma16816(float* c, const uint32_t* a, const uint32_t* b) {
    asm volatile("mma.sync.aligned.m16n8k16.row.col.f32.bf16.bf16.f32 "
        "{%0,%1,%2,%3}, {%4,%5,%6,%7}, {%8,%9}, {%0,%1,%2,%3};"
        : "+f"(c[0]), "+f"(c[1]), "+f"(c[2]), "+f"(c[3])
        : "r"(a[0]), "r"(a[1]), "r"(a[2]), "r"(a[3]), "r"(b[0]), "r"(b[1]));
}

__device__ __forceinline__ void split1(float v, ushort_t& h, ushort_t& l) {
    __nv_bfloat16 hb = __float2bfloat16(v);
    h = __bfloat16_as_ushort(hb);
    l = __bfloat16_as_ushort(__float2bfloat16(v - __bfloat162float(hb)));
}

// ---------------- weight transpose + bf16 hi/lo split: T[n][k] = W[k][n] ----------------
__global__ void __launch_bounds__(256) wsplit_t(
    const float* __restrict__ W,
    ushort_t* __restrict__ Th, ushort_t* __restrict__ Tl)
{
    __shared__ float ts[32][33];
    int n0 = blockIdx.x * 32, k0 = blockIdx.y * 32;
    int tx = threadIdx.x & 31, ty = threadIdx.x >> 5;
#pragma unroll
    for (int e = 0; e < 4; e++)
        ts[ty + 8*e][tx] = W[(size_t)(k0 + ty + 8*e)*C_ + n0 + tx];
    __syncthreads();
#pragma unroll
    for (int e = 0; e < 4; e++) {
        int n = ty + 8*e;
        float v = ts[tx][n];
        ushort_t h, l;
        split1(v, h, l);
        Th[(size_t)(n0+n)*C_ + k0 + tx] = h;
        Tl[(size_t)(n0+n)*C_ + k0 + tx] = l;
    }
}

// ---------------- bf16x3 HMMA GEMM: C[M,N] = A[M,K] @ B[K,N] ----------------
// CTA 128(M) x 256(N), 512 threads (16 warps, 4x4 grid), warp tile 32x64,
// K-chunk 32, 3-stage cp.async pipe (prefetch-after-wait schedule).
// Batched over blockIdx.z via a pointer table passed by value.
#define LDB     80            // padded row bytes (40 bf16): conflict-free ldmatrix
#define SZ_A    (128*LDB)     // 10240 per A buffer
#define SZ_B    (256*LDB)     // 20480 per B buffer
#define STAGE_B (2*SZ_A + 2*SZ_B)   // Ah, Al, Bh, Bl = 61440
#define NSTAGE  3
#define GEMM_SMEM (NSTAGE*STAGE_B)  // 184320

struct GemmBatch {
    const ushort_t* Ah[4];
    const ushort_t* Al[4];
    const ushort_t* Bh[4];
    const ushort_t* Bl[4];
    float*          Cm[4];
};

__device__ __forceinline__ void gemm_load_stage(
    uint32_t sb, int s, const ushort_t* Ah, const ushort_t* Al,
    const ushort_t* Bh, const ushort_t* Bl, int m0, int n0, int kt, int tid)
{
    int k0 = kt * 32;
    uint32_t base = sb + s*STAGE_B;
    {
        int row = tid >> 2, c = tid & 3;
        uint32_t d = base + row*LDB + c*16;
        size_t offA = (size_t)(m0 + row)*C_ + k0 + c*8;
        cp16(d,        Ah + offA);
        cp16(d + SZ_A, Al + offA);
    }
#pragma unroll
    for (int e = 0; e < 2; e++) {
        int q = tid + 512*e;
        int row = q >> 2, c = q & 3;
        uint32_t d = base + 2*SZ_A + row*LDB + c*16;
        size_t offB = (size_t)(n0 + row)*C_ + k0 + c*8;
        cp16(d,        Bh + offB);
        cp16(d + SZ_B, Bl + offB);
    }
    CP_COMMIT();
}

__device__ __forceinline__ void gemm_core(
    const ushort_t* __restrict__ Ah, const ushort_t* __restrict__ Al,
    const ushort_t* __restrict__ Bh, const ushort_t* __restrict__ Bl,
    float* __restrict__ Cm, char* smem)
{
    uint32_t sb = smem_u32(smem);
    int tid = threadIdx.x, lane = tid & 31, w = tid >> 5;
    int wm = w & 3, wn = w >> 2;           // 4 x 4 warp grid (M x N)
    int m0 = blockIdx.y * 128, n0 = blockIdx.x * 256;

    float acc[2][8][4];
#pragma unroll
    for (int i = 0; i < 2; i++)
#pragma unroll
        for (int j = 0; j < 8; j++)
#pragma unroll
            for (int q = 0; q < 4; q++) acc[i][j][q] = 0.f;

    gemm_load_stage(sb, 0, Ah, Al, Bh, Bl, m0, n0, 0, tid);
    gemm_load_stage(sb, 1, Ah, Al, Bh, Bl, m0, n0, 1, tid);

    uint32_t a_off = (uint32_t)((wm*32 + (lane & 15))*LDB + (lane >> 4)*16);
    uint32_t b_off = (uint32_t)((wn*64 + (lane & 7) + ((lane >> 4) & 1)*8)*LDB
                                + ((lane >> 3) & 1)*16);

    for (int kt = 0; kt < C_/32; kt++) {
        int s = kt % NSTAGE;
        CP_WAIT1();
        __syncthreads();
        if (kt + 2 < C_/32)
            gemm_load_stage(sb, (kt+2) % NSTAGE, Ah, Al, Bh, Bl, m0, n0, kt+2, tid);

        uint32_t base = sb + s*STAGE_B;
#pragma unroll
        for (int kk = 0; kk < 2; kk++) {
            uint32_t ah[2][4], al[2][4], bh[4][4], bl[4][4];
#pragma unroll
            for (int mt = 0; mt < 2; mt++) {
                uint32_t addr = base + a_off + mt*16*LDB + kk*32;
                ldsm_x4(ah[mt], addr);
                ldsm_x4(al[mt], addr + SZ_A);
            }
#pragma unroll
            for (int g = 0; g < 4; g++) {
                uint32_t addr = base + 2*SZ_A + b_off + g*16*LDB + kk*32;
                ldsm_x4(bh[g], addr);
                ldsm_x4(bl[g], addr + SZ_B);
            }
#pragma unroll
            for (int mt = 0; mt < 2; mt++)
#pragma unroll
                for (int nt = 0; nt < 8; nt++) {
                    const uint32_t* bph = &bh[nt >> 1][(nt & 1)*2];
                    const uint32_t* bpl = &bl[nt >> 1][(nt & 1)*2];
                    mma16816(acc[mt][nt], ah[mt], bph);   // hh
                    mma16816(acc[mt][nt], ah[mt], bpl);   // h*lo
                    mma16816(acc[mt][nt], al[mt], bph);   // lo*h
                }
        }
    }

#pragma unroll
    for (int mt = 0; mt < 2; mt++) {
        int r0 = m0 + wm*32 + mt*16 + (lane >> 2);
#pragma unroll
        for (int nt = 0; nt < 8; nt++) {
            int c0 = n0 + wn*64 + nt*8 + (lane & 3)*2;
            *(float2*)&Cm[(size_t)r0*C_ + c0] =
                make_float2(acc[mt][nt][0], acc[mt][nt][1]);
            *(float2*)&Cm[(size_t)(r0+8)*C_ + c0] =
                make_float2(acc[mt][nt][2], acc[mt][nt][3]);
        }
    }
}

// batched over z
__global__ void __launch_bounds__(512, 1) gemm_bf3b(GemmBatch gb)
{
    extern __shared__ char smem[];
    int z = blockIdx.z;
    gemm_core(gb.Ah[z], gb.Al[z], gb.Bh[z], gb.Bl[z], gb.Cm[z], smem);
}

// single
__global__ void __launch_bounds__(512, 1) gemm_bf3(
    const ushort_t* __restrict__ Ah, const ushort_t* __restrict__ Al,
    const ushort_t* __restrict__ Bh, const ushort_t* __restrict__ Bl,
    float* __restrict__ Cm)
{
    extern __shared__ char smem[];
    gemm_core(Ah, Al, Bh, Bl, Cm, smem);
}

// ---------------- skinny GEMM + tanh ----------------
template<int NS, bool FUSE>
__global__ void __launch_bounds__(256) skinny_tanh_gemm(
    const float* __restrict__ A, const float* __restrict__ W,
    float* __restrict__ out,
    const float* __restrict__ shift, const float* __restrict__ maax)
{
    __shared__ float As[32*68];
    __shared__ float Ws[32*NS];
    const int tid = threadIdx.x;
    const int m0  = blockIdx.x * 64;
    const int row = tid >> 2;
    const int cg  = tid & 3;

    float acc[NS/4];
#pragma unroll
    for (int i = 0; i < NS/4; i++) acc[i] = 0.f;

    for (int k0 = 0; k0 < C_; k0 += 32) {
#pragma unroll
        for (int e = 0; e < 2; e++) {
            int q  = tid + 256*e;
            int r  = q >> 3;
            int c4 = (q & 7) * 4;
            int m  = m0 + r;
            float4 val;
            if (FUSE) {
                float4 xv = *(const float4*)(A + (size_t)m*C_ + k0 + c4);
                int t = m & (T_-1);
                int b = m >> 11;
                float4 xp = (t > 0) ? *(const float4*)(A + (size_t)(m-1)*C_ + k0 + c4)
                                    : *(const float4*)(shift + (size_t)b*C_ + k0 + c4);
                float4 mx = *(const float4*)(maax + k0 + c4);
                val.x = xv.x + (xp.x - xv.x)*mx.x;
                val.y = xv.y + (xp.y - xv.y)*mx.y;
                val.z = xv.z + (xp.z - xv.z)*mx.z;
                val.w = xv.w + (xp.w - xv.w)*mx.w;
            } else {
                val = *(const float4*)(A + (size_t)m*C_ + k0 + c4);
            }
            As[(c4+0)*68 + r] = val.x;
            As[(c4+1)*68 + r] = val.y;
            As[(c4+2)*68 + r] = val.z;
            As[(c4+3)*68 + r] = val.w;
        }
        {
            const float4* src = (const float4*)(W + (size_t)k0*NS);
            for (int q = tid; q < 32*NS/4; q += 256)
                ((float4*)Ws)[q] = src[q];
        }
        __syncthreads();
#pragma unroll 8
        for (int k = 0; k < 32; k++) {
            float a = As[k*68 + row];
            const float* wrow = Ws + k*NS + cg*(NS/4);
#pragma unroll
            for (int j = 0; j < NS/16; j++) {
                float4 w4 = *(const float4*)(wrow + j*4);
                acc[j*4+0] = fmaf(a, w4.x, acc[j*4+0]);
                acc[j*4+1] = fmaf(a, w4.y, acc[j*4+1]);
                acc[j*4+2] = fmaf(a, w4.z, acc[j*4+2]);
                acc[j*4+3] = fmaf(a, w4.w, acc[j*4+3]);
            }
        }
        __syncthreads();
    }
    float* orow = out + (size_t)(m0+row)*NS + cg*(NS/4);
#pragma unroll
    for (int i = 0; i < NS/4; i++) orow[i] = tanhf(acc[i]);
}

// ---------------- 5-way mix apply, per-f, templated output mode ----------------
// MODE 0: bf16 hi/lo split only.  MODE 1: fp32 only.  MODE 2: fp32 + split.
template<int MODE>
__global__ void __launch_bounds__(256) mix_apply_f(
    const float* __restrict__ x, const float* __restrict__ shift,
    const float* __restrict__ tm, const float* __restrict__ w2,
    const float* __restrict__ maa,
    ushort_t* __restrict__ oh, ushort_t* __restrict__ ol,
    float* __restrict__ of, int f)
{
    __shared__ float tmf[32*32];
    __shared__ float w2f[32*64];
    int tid = threadIdx.x;
    int m0 = blockIdx.y * 32;
    int c0 = blockIdx.x * 64;
    {
        int r = tid >> 3, c4 = (tid & 7) * 4;
        *(float4*)&tmf[r*32 + c4] =
            *(const float4*)(tm + (size_t)(m0+r)*160 + f*32 + c4);
    }
#pragma unroll
    for (int e = 0; e < 2; e++) {
        int q = tid + 256*e;
        int d = q >> 4, c4 = (q & 15) * 4;
        *(float4*)&w2f[d*64 + c4] =
            *(const float4*)(w2 + (size_t)(f*32+d)*C_ + c0 + c4);
    }
    __syncthreads();
#pragma unroll
    for (int e = 0; e < 2; e++) {
        int p = tid + 256*e;
        int r  = p >> 4;
        int c4 = (p & 15) * 4;
        int m = m0 + r;
        int c = c0 + c4;
        float4 acc = make_float4(0.f,0.f,0.f,0.f);
#pragma unroll
        for (int d = 0; d < 32; d++) {
            float tv = tmf[r*32 + d];
            float4 w4 = *(const float4*)&w2f[d*64 + c4];
            acc.x = fmaf(tv, w4.x, acc.x);
            acc.y = fmaf(tv, w4.y, acc.y);
            acc.z = fmaf(tv, w4.z, acc.z);
            acc.w = fmaf(tv, w4.w, acc.w);
        }
        float4 xv = *(const float4*)(x + (size_t)m*C_ + c);
        int t = m & (T_-1), b = m >> 11;
        float4 xp = (t > 0) ? *(const float4*)(x + (size_t)(m-1)*C_ + c)
                            : *(const float4*)(shift + (size_t)b*C_ + c);
        float4 ma = *(const float4*)(maa + c);
        float4 o;
        o.x = xv.x + (xp.x - xv.x)*(ma.x + acc.x);
        o.y = xv.y + (xp.y - xv.y)*(ma.y + acc.y);
        o.z = xv.z + (xp.z - xv.z)*(ma.z + acc.z);
        o.w = xv.w + (xp.w - xv.w)*(ma.w + acc.w);
        size_t base = (size_t)m*C_ + c;
        if (MODE == 1 || MODE == 2)
            *(float4*)(of + base) = o;
        if (MODE == 0 || MODE == 2) {
            ushort4 h4, l4;
            split1(o.x, h4.x, l4.x);
            split1(o.y, h4.y, l4.y);
            split1(o.z, h4.z, l4.z);
            split1(o.w, h4.w, l4.w);
            *(ushort4*)(oh + base) = h4;
            *(ushort4*)(ol + base) = l4;
        }
    }
}

// ---------------- small-K GEMM (K=64) with fused epilogues ----------------
// MODE 0: d = exp(-exp(td + A@W)); store d only (k scaling moved into wkv_scan)
// MODE 1: out1 += A@W
template<int MODE>
__global__ void __launch_bounds__(256) smallk_gemm(
    const float* __restrict__ A, const float* __restrict__ W,
    const float* __restrict__ td, float* __restrict__ out1)
{
    __shared__ float As[32*64];
    __shared__ float Ws[64*128];
    int tid = threadIdx.x;
    int m0 = blockIdx.y * 32, c0 = blockIdx.x * 128;
    {
        const float4* src = (const float4*)(A + (size_t)m0*64);
#pragma unroll
        for (int q = tid; q < 512; q += 256) ((float4*)As)[q] = src[q];
    }
#pragma unroll
    for (int e = 0; e < 8; e++) {
        int q = tid + 256*e;
        int kr = q >> 5, c4 = (q & 31) * 4;
        *(float4*)&Ws[kr*128 + c4] = *(const float4*)(W + (size_t)kr*C_ + c0 + c4);
    }
    __syncthreads();
    int ty = tid >> 4, tx = tid & 15;
    int r0 = ty * 2;
    float acc[2][8];
#pragma unroll
    for (int i = 0; i < 2; i++)
#pragma unroll
        for (int j = 0; j < 8; j++) acc[i][j] = 0.f;
#pragma unroll
    for (int k = 0; k < 64; k++) {
        float a0 = As[r0*64 + k];
        float a1 = As[(r0+1)*64 + k];
        float4 b0 = *(const float4*)&Ws[k*128 + tx*8];
        float4 b1 = *(const float4*)&Ws[k*128 + tx*8 + 4];
        float bv[8] = {b0.x,b0.y,b0.z,b0.w,b1.x,b1.y,b1.z,b1.w};
#pragma unroll
        for (int j = 0; j < 8; j++) {
            acc[0][j] = fmaf(a0, bv[j], acc[0][j]);
            acc[1][j] = fmaf(a1, bv[j], acc[1][j]);
        }
    }
#pragma unroll
    for (int rr = 0; rr < 2; rr++) {
        int m = m0 + r0 + rr;
        size_t base = (size_t)m*C_ + c0 + tx*8;
        if (MODE == 0) {
#pragma unroll
            for (int j = 0; j < 8; j++) {
                float w = td[c0 + tx*8 + j] + acc[rr][j];
                out1[base + j] = expf(-expf(w));
            }
        } else {
#pragma unroll
            for (int j = 0; j < 8; j++) out1[base + j] += acc[rr][j];
        }
    }
}

// ---------------- WKV scan (k*(1-d) fused in) ----------------
__global__ void __launch_bounds__(64) wkv_scan(
    const float* __restrict__ rp, const float* __restrict__ kp,
    const float* __restrict__ vp, const float* __restrict__ dp,
    const float* __restrict__ S0, float* __restrict__ yp,
    float* __restrict__ Sout)
{
    int bh = blockIdx.x;
    int j = threadIdx.x;
    int b = bh >> 5, h = bh & (H_-1);
    float S[64];
    const float* s0 = S0 + (size_t)bh*HS_*HS_ + j;
#pragma unroll
    for (int i = 0; i < 64; i++) S[i] = s0[(size_t)i*64];
    __shared__ float4 skd[64];
    size_t idx = (size_t)b*T_*C_ + (size_t)h*64 + j;
    float rr = rp[idx], kk = kp[idx], dd = dp[idx], vv = vp[idx];
    for (int t = 0; t < T_; t++) {
        float rn = 0.f, kn = 0.f, dn = 0.f, vn = 0.f;
        if (t + 1 < T_) {
            size_t nx = idx + C_;
            rn = rp[nx]; kn = kp[nx]; dn = dp[nx]; vn = vp[nx];
        }
        skd[j] = make_float4(rr, kk * (1.0f - dd), dd, 0.f);
        __syncthreads();
        float acc = 0.f;
#pragma unroll
        for (int i = 0; i < 64; i++) {
            float4 q = skd[i];
            acc  = fmaf(q.x, S[i], acc);
            S[i] = fmaf(q.z, S[i], q.y * vv);
        }
        yp[idx] = acc;
        __syncthreads();
        idx += C_;
        rr = rn; kk = kn; dd = dn; vv = vn;
    }
    float* so = Sout + (size_t)bh*HS_*HS_ + j;
#pragma unroll
    for (int i = 0; i < 64; i++) so[(size_t)i*64] = S[i];
}

// ---------------- fused add + LayerNorm, emits bf16 hi/lo split ----------------
__global__ void __launch_bounds__(256) ln_add_split(
    const float* __restrict__ a, const float* __restrict__ b,
    const float* __restrict__ lw, const float* __restrict__ lb,
    ushort_t* __restrict__ oh, ushort_t* __restrict__ ol)
{
    int m = blockIdx.x;
    int tid = threadIdx.x;
    const float* ar = a + (size_t)m*C_;
    const float* br = b + (size_t)m*C_;
    float vals[8];
    float s = 0.f, s2 = 0.f;
#pragma unroll
    for (int i = 0; i < 8; i++) {
        int c = tid + 256*i;
        float u = ar[c] + br[c];
        vals[i] = u; s += u; s2 = fmaf(u, u, s2);
    }
#pragma unroll
    for (int o = 16; o > 0; o >>= 1) {
        s  += __shfl_xor_sync(0xffffffffu, s,  o);
        s2 += __shfl_xor_sync(0xffffffffu, s2, o);
    }
    __shared__ float sa[8], sb2[8];
    if ((tid & 31) == 0) { sa[tid>>5] = s; sb2[tid>>5] = s2; }
    __syncthreads();
    s = 0.f; s2 = 0.f;
#pragma unroll
    for (int i = 0; i < 8; i++) { s += sa[i]; s2 += sb2[i]; }
    float mu  = s * (1.0f/C_);
    float var = s2 * (1.0f/C_) - mu*mu;
    float inv = rsqrtf(var + 1e-5f);
#pragma unroll
    for (int i = 0; i < 8; i++) {
        int c = tid + 256*i;
        float v = (vals[i] - mu)*inv*lw[c] + lb[c];
        ushort_t h, l;
        split1(v, h, l);
        oh[(size_t)m*C_ + c] = h;
        ol[(size_t)m*C_ + c] = l;
    }
}

__global__ void copy_xlast(const float* __restrict__ x, float* __restrict__ o)
{
    int i = blockIdx.x*256 + threadIdx.x;
    int b = i >> 11, c = i & (C_-1);
    o[i] = x[((size_t)b*T_ + (T_-1))*C_ + c];
}

// ---------------- launcher ----------------
extern "C" void kernel_launch(void* const* d_in, const int* in_sizes, int n_in,
                              void* d_out, int out_size)
{
    (void)in_sizes; (void)n_in;
    const float* x     = (const float*)d_in[0];
    const float* shift = (const float*)d_in[1];
    const float* wkv0  = (const float*)d_in[2];
    const float* maax  = (const float*)d_in[3];
    const float* maar  = (const float*)d_in[4];
    const float* maak  = (const float*)d_in[5];
    const float* maav  = (const float*)d_in[6];
    const float* maaw  = (const float*)d_in[7];
    const float* maav2 = (const float*)d_in[8];
    const float* w1    = (const float*)d_in[9];
    const float* w2    = (const float*)d_in[10];
    const float* tdec  = (const float*)d_in[11];
    const float* dw1   = (const float*)d_in[12];
    const float* dw2   = (const float*)d_in[13];
    const float* vw1   = (const float*)d_in[14];
    const float* vw2   = (const float*)d_in[15];
    const float* Wr    = (const float*)d_in[17];
    const float* Wk    = (const float*)d_in[18];
    const float* Wv    = (const float*)d_in[19];
    const float* Wo    = (const float*)d_in[20];
    const float* lnw   = (const float*)d_in[21];
    const float* lnb   = (const float*)d_in[22];
    float* out = (float*)d_out;

    float *tm,*xrf,*xkf,*xvf,*xw,*xv2,*rb,*kb,*vb,*v2b,*db,*lwv,*lv2,*yw;
    ushort_t *ah,*al,*wrh,*wrl,*wkh,*wkl,*wvh,*wvl,*woh,*wol;
    cudaGetSymbolAddress((void**)&tm,  g_tm);
    cudaGetSymbolAddress((void**)&xrf, g_xr);
    cudaGetSymbolAddress((void**)&xkf, g_xk);
    cudaGetSymbolAddress((void**)&xvf, g_xv);
    cudaGetSymbolAddress((void**)&xw,  g_xw);
    cudaGetSymbolAddress((void**)&xv2, g_xv2);
    cudaGetSymbolAddress((void**)&rb,  g_r);
    cudaGetSymbolAddress((void**)&kb,  g_k);
    cudaGetSymbolAddress((void**)&vb,  g_v);
    cudaGetSymbolAddress((void**)&v2b, g_v2);
    cudaGetSymbolAddress((void**)&db,  g_d);
    cudaGetSymbolAddress((void**)&lwv, g_lw);
    cudaGetSymbolAddress((void**)&lv2, g_lv2);
    cudaGetSymbolAddress((void**)&yw,  g_yw);
    cudaGetSymbolAddress((void**)&ah,  g_ah);
    cudaGetSymbolAddress((void**)&al,  g_al);
    cudaGetSymbolAddress((void**)&wrh, g_wrh);
    cudaGetSymbolAddress((void**)&wrl, g_wrl);
    cudaGetSymbolAddress((void**)&wkh, g_wkh);
    cudaGetSymbolAddress((void**)&wkl, g_wkl);
    cudaGetSymbolAddress((void**)&wvh, g_wvh);
    cudaGetSymbolAddress((void**)&wvl, g_wvl);
    cudaGetSymbolAddress((void**)&woh, g_woh);
    cudaGetSymbolAddress((void**)&wol, g_wol);

    // xr/xk/xv fp32 buffers reinterpreted as bf16 hi/lo pairs
    ushort_t* xrh = (ushort_t*)xrf; ushort_t* xrl = xrh + (size_t)M_*C_;
    ushort_t* xkh = (ushort_t*)xkf; ushort_t* xkl = xkh + (size_t)M_*C_;
    ushort_t* xvh = (ushort_t*)xvf; ushort_t* xvl = xvh + (size_t)M_*C_;

    cudaFuncSetAttribute(gemm_bf3,  cudaFuncAttributeMaxDynamicSharedMemorySize, GEMM_SMEM);
    cudaFuncSetAttribute(gemm_bf3b, cudaFuncAttributeMaxDynamicSharedMemorySize, GEMM_SMEM);

    // 0) weight transpose + bf16 split
    {
        dim3 gt(C_/32, C_/32);
        wsplit_t<<<gt,256>>>(Wr, wrh, wrl);
        wsplit_t<<<gt,256>>>(Wk, wkh, wkl);
        wsplit_t<<<gt,256>>>(Wv, wvh, wvl);
        wsplit_t<<<gt,256>>>(Wo, woh, wol);
    }

    // 1) LoRA-5 projection with fused token-shift mixing
    skinny_tanh_gemm<160, true><<<M_/64, 256>>>(x, w1, tm, shift, maax);

    // 2) 5-way mix (split emitted in-kernel)
    {
        dim3 g(C_/64, M_/32);
        mix_apply_f<0><<<g,256>>>(x, shift, tm, w2, maar,  xrh, xrl, nullptr, 0);
        mix_apply_f<0><<<g,256>>>(x, shift, tm, w2, maak,  xkh, xkl, nullptr, 1);
        mix_apply_f<0><<<g,256>>>(x, shift, tm, w2, maav,  xvh, xvl, nullptr, 2);
        mix_apply_f<1><<<g,256>>>(x, shift, tm, w2, maaw,  nullptr, nullptr, xw, 3);
        mix_apply_f<2><<<g,256>>>(x, shift, tm, w2, maav2, ah, al, xv2, 4);
    }

    // 3) big projections via batched HMMA bf16x3 (z = r, k, v, v2)
    {
        GemmBatch gb;
        gb.Ah[0]=xrh; gb.Al[0]=xrl; gb.Bh[0]=wrh; gb.Bl[0]=wrl; gb.Cm[0]=rb;
        gb.Ah[1]=xkh; gb.Al[1]=xkl; gb.Bh[1]=wkh; gb.Bl[1]=wkl; gb.Cm[1]=kb;
        gb.Ah[2]=xvh; gb.Al[2]=xvl; gb.Bh[2]=wvh; gb.Bl[2]=wvl; gb.Cm[2]=vb;
        gb.Ah[3]=ah;  gb.Al[3]=al;  gb.Bh[3]=wvh; gb.Bl[3]=wvl; gb.Cm[3]=v2b;
        dim3 gb4(C_/256, M_/128, 4);
        gemm_bf3b<<<gb4,512,GEMM_SMEM>>>(gb);
    }

    // 4) decay / value2 LoRAs
    skinny_tanh_gemm<64, false><<<M_/64, 256>>>(xw,  dw1, lwv, nullptr, nullptr);
    skinny_tanh_gemm<64, false><<<M_/64, 256>>>(xv2, vw1, lv2, nullptr, nullptr);
    {
        dim3 gs(C_/128, M_/32);
        smallk_gemm<0><<<gs,256>>>(lwv, dw2, tdec, db);      // d only
        smallk_gemm<1><<<gs,256>>>(lv2, vw2, nullptr, v2b);  // v2 += lora
    }

    // 5) WKV scan (k*(1-d) inline), 6) add v2 + LayerNorm, 7) output projection
    const size_t OFFS = (size_t)M_*C_;
    const size_t OFFX = OFFS + (size_t)B_*H_*HS_*HS_;
    bool full = (size_t)out_size >= OFFX + (size_t)B_*C_;
    float* Sout = full ? (out + OFFS) : tm;
    wkv_scan<<<B_*H_, 64>>>(rb, kb, vb, db, wkv0, yw, Sout);
    ln_add_split<<<M_, 256>>>(yw, v2b, lnw, lnb, ah, al);
    dim3 gg(C_/256, M_/128);
    gemm_bf3<<<gg,512,GEMM_SMEM>>>(ah, al, woh, wol, out);
    if (full) copy_xlast<<<(B_*C_)/256, 256>>>(x, out + OFFX);
}

// round 12
// speedup vs baseline: 1.5679x; 1.2265x over previous
#include <cuda_runtime.h>
#include <cuda_fp16.h>
#include <math.h>
#include <stdint.h>

#define B_ 8
#define T_ 2048
#define C_ 2048
#define H_ 32
#define HS_ 64
#define M_ (B_*T_)   // 16384

typedef unsigned short ushort_t;

// ---------------- scratch (__device__ globals: allocation-free) ----------------
__device__ float g_tm [(size_t)M_*160];
__device__ float g_xr [(size_t)M_*C_];   // holds fp16 hi/lo split of xr
__device__ float g_xk [(size_t)M_*C_];   // holds fp16 hi/lo split of xk
__device__ float g_xv [(size_t)M_*C_];   // holds fp16 hi/lo split of xv
__device__ float g_xw [(size_t)M_*C_];
__device__ float g_xv2[(size_t)M_*C_];
__device__ float g_r  [(size_t)M_*C_];
__device__ float g_k  [(size_t)M_*C_];
__device__ float g_v  [(size_t)M_*C_];
__device__ float g_v2 [(size_t)M_*C_];
__device__ float g_d  [(size_t)M_*C_];
__device__ float g_lw [(size_t)M_*64];
__device__ float g_lv2[(size_t)M_*64];
__device__ float g_yw [(size_t)M_*C_];

// fp16 hi/lo split scratch (xv2 split, later yln split)
__device__ ushort_t g_ah[(size_t)M_*C_];
__device__ ushort_t g_al[(size_t)M_*C_];

// transposed fp16 weights: [N, K] (single precision level; A-side carries the split)
__device__ ushort_t g_wr[(size_t)C_*C_];
__device__ ushort_t g_wk[(size_t)C_*C_];
__device__ ushort_t g_wv[(size_t)C_*C_];
__device__ ushort_t g_wo[(size_t)C_*C_];

// ================= low-level helpers (base-target PTX only) =================
__device__ __forceinline__ uint32_t smem_u32(const void* p) {
    uint32_t a;
    asm("{ .reg .u64 t; cvta.to.shared.u64 t, %1; cvt.u32.u64 %0, t; }" : "=r"(a) : "l"(p));
    return a;
}
__device__ __forceinline__ void cp16(uint32_t dst, const void* src) {
    asm volatile("cp.async.cg.shared.global [%0], [%1], 16;" :: "r"(dst), "l"(src) : "memory");
}
#define CP_COMMIT() asm volatile("cp.async.commit_group;" ::: "memory")
#define CP_WAIT1()  asm volatile("cp.async.wait_group 1;"  ::: "memory")

__device__ __forceinline__ void ldsm_x4(uint32_t* r, uint32_t a) {
    asm volatile("ldmatrix.sync.aligned.m8n8.x4.shared.b16 {%0,%1,%2,%3}, [%4];"
        : "=r"(r[0]), "=r"(r[1]), "=r"(r[2]), "=r"(r[3]) : "r"(a));
}
__device__ __forceinline__ void mma16816h(float* c, const uint32_t* a, const uint32_t* b) {
    asm volatile("mma.sync.aligned.m16n8k16.row.col.f32.f16.f16.f32 "
        "{%0,%1,%2,%3}, {%4,%5,%6,%7}, {%8,%9}, {%0,%1,%2,%3};"
        : "+f"(c[0]), "+f"(c[1]), "+f"(c[2]), "+f"(c[3])
        : "r"(a[0]), "r"(a[1]), "r"(a[2]), "r"(a[3]), "r"(b[0]), "r"(b[1]));
}

__device__ __forceinline__ void split1(float v, ushort_t& h, ushort_t& l) {
    __half hb = __float2half_rn(v);
    h = __half_as_ushort(hb);
    l = __half_as_ushort(__float2half_rn(v - __half2float(hb)));
}

// ---------------- weight transpose + fp16 convert: T[n][k] = fp16(W[k][n]) ----------------
__global__ void __launch_bounds__(256) wsplit_t(
    const float* __restrict__ W, ushort_t* __restrict__ Th)
{
    __shared__ float ts[32][33];
    int n0 = blockIdx.x * 32, k0 = blockIdx.y * 32;
    int tx = threadIdx.x & 31, ty = threadIdx.x >> 5;
#pragma unroll
    for (int e = 0; e < 4; e++)
        ts[ty + 8*e][tx] = W[(size_t)(k0 + ty + 8*e)*C_ + n0 + tx];
    __syncthreads();
#pragma unroll
    for (int e = 0; e < 4; e++) {
        int n = ty + 8*e;
        Th[(size_t)(n0+n)*C_ + k0 + tx] =
            __half_as_ushort(__float2half_rn(ts[tx][n]));
    }
}

// ---------------- fp16x2 HMMA GEMM: C[M,N] = A[M,K] @ B[K,N] ----------------
// A hi/lo fp16 [M,K] row-major, B = fp16(W^T) [N,K] row-major, C fp32.
// acc = ah@B + al@B  (residual = A * (W - fp16(W)) ~ 2^-11 relative).
// CTA 128(M) x 256(N), 512 threads (16 warps, 4x4), warp tile 32x64,
// K-chunk 32, 3-stage cp.async pipe (prefetch-after-wait schedule).
#define LDB     80            // padded row bytes (40 fp16): conflict-free ldmatrix
#define SZ_A    (128*LDB)     // 10240 per A buffer
#define SZ_B    (256*LDB)     // 20480 for B
#define STAGE_B (2*SZ_A + SZ_B)     // Ah, Al, B = 40960
#define NSTAGE  3
#define GEMM_SMEM (NSTAGE*STAGE_B)  // 122880

struct GemmBatch {
    const ushort_t* Ah[4];
    const ushort_t* Al[4];
    const ushort_t* Bh[4];
    float*          Cm[4];
};

__device__ __forceinline__ void gemm_load_stage(
    uint32_t sb, int s, const ushort_t* Ah, const ushort_t* Al,
    const ushort_t* Bh, int m0, int n0, int kt, int tid)
{
    int k0 = kt * 32;
    uint32_t base = sb + s*STAGE_B;
    // A: 128 rows x 4 chunks (hi+lo) — 512 threads, 1 chunk each
    {
        int row = tid >> 2, c = tid & 3;
        uint32_t d = base + row*LDB + c*16;
        size_t offA = (size_t)(m0 + row)*C_ + k0 + c*8;
        cp16(d,        Ah + offA);
        cp16(d + SZ_A, Al + offA);
    }
    // B: 256 rows x 4 chunks — 2 chunks each
#pragma unroll
    for (int e = 0; e < 2; e++) {
        int q = tid + 512*e;
        int row = q >> 2, c = q & 3;
        uint32_t d = base + 2*SZ_A + row*LDB + c*16;
        size_t offB = (size_t)(n0 + row)*C_ + k0 + c*8;
        cp16(d, Bh + offB);
    }
    CP_COMMIT();
}

__device__ __forceinline__ void gemm_core(
    const ushort_t* __restrict__ Ah, const ushort_t* __restrict__ Al,
    const ushort_t* __restrict__ Bh, float* __restrict__ Cm, char* smem)
{
    uint32_t sb = smem_u32(smem);
    int tid = threadIdx.x, lane = tid & 31, w = tid >> 5;
    int wm = w & 3, wn = w >> 2;           // 4 x 4 warp grid (M x N)
    int m0 = blockIdx.y * 128, n0 = blockIdx.x * 256;

    float acc[2][8][4];
#pragma unroll
    for (int i = 0; i < 2; i++)
#pragma unroll
        for (int j = 0; j < 8; j++)
#pragma unroll
            for (int q = 0; q < 4; q++) acc[i][j][q] = 0.f;

    gemm_load_stage(sb, 0, Ah, Al, Bh, m0, n0, 0, tid);
    gemm_load_stage(sb, 1, Ah, Al, Bh, m0, n0, 1, tid);

    uint32_t a_off = (uint32_t)((wm*32 + (lane & 15))*LDB + (lane >> 4)*16);
    uint32_t b_off = (uint32_t)((wn*64 + (lane & 7) + ((lane >> 4) & 1)*8)*LDB
                                + ((lane >> 3) & 1)*16);

    for (int kt = 0; kt < C_/32; kt++) {
        int s = kt % NSTAGE;
        CP_WAIT1();
        __syncthreads();
        if (kt + 2 < C_/32)
            gemm_load_stage(sb, (kt+2) % NSTAGE, Ah, Al, Bh, m0, n0, kt+2, tid);

        uint32_t base = sb + s*STAGE_B;
#pragma unroll
        for (int kk = 0; kk < 2; kk++) {
            uint32_t ah[2][4], al[2][4], bb[4][4];
#pragma unroll
            for (int mt = 0; mt < 2; mt++) {
                uint32_t addr = base + a_off + mt*16*LDB + kk*32;
                ldsm_x4(ah[mt], addr);
                ldsm_x4(al[mt], addr + SZ_A);
            }
#pragma unroll
            for (int g = 0; g < 4; g++) {
                uint32_t addr = base + 2*SZ_A + b_off + g*16*LDB + kk*32;
                ldsm_x4(bb[g], addr);
            }
#pragma unroll
            for (int mt = 0; mt < 2; mt++)
#pragma unroll
                for (int nt = 0; nt < 8; nt++) {
                    const uint32_t* bp = &bb[nt >> 1][(nt & 1)*2];
                    mma16816h(acc[mt][nt], ah[mt], bp);   // ah * b
                    mma16816h(acc[mt][nt], al[mt], bp);   // al * b
                }
        }
    }

#pragma unroll
    for (int mt = 0; mt < 2; mt++) {
        int r0 = m0 + wm*32 + mt*16 + (lane >> 2);
#pragma unroll
        for (int nt = 0; nt < 8; nt++) {
            int c0 = n0 + wn*64 + nt*8 + (lane & 3)*2;
            *(float2*)&Cm[(size_t)r0*C_ + c0] =
                make_float2(acc[mt][nt][0], acc[mt][nt][1]);
            *(float2*)&Cm[(size_t)(r0+8)*C_ + c0] =
                make_float2(acc[mt][nt][2], acc[mt][nt][3]);
        }
    }
}

__global__ void __launch_bounds__(512, 1) gemm_bf3b(GemmBatch gb)
{
    extern __shared__ char smem[];
    int z = blockIdx.z;
    gemm_core(gb.Ah[z], gb.Al[z], gb.Bh[z], gb.Cm[z], smem);
}

__global__ void __launch_bounds__(512, 1) gemm_bf3(
    const ushort_t* __restrict__ Ah, const ushort_t* __restrict__ Al,
    const ushort_t* __restrict__ Bh, float* __restrict__ Cm)
{
    extern __shared__ char smem[];
    gemm_core(Ah, Al, Bh, Cm, smem);
}

// ---------------- skinny GEMM + tanh ----------------
template<int NS, bool FUSE>
__global__ void __launch_bounds__(256) skinny_tanh_gemm(
    const float* __restrict__ A, const float* __restrict__ W,
    float* __restrict__ out,
    const float* __restrict__ shift, const float* __restrict__ maax)
{
    __shared__ float As[32*68];
    __shared__ float Ws[32*NS];
    const int tid = threadIdx.x;
    const int m0  = blockIdx.x * 64;
    const int row = tid >> 2;
    const int cg  = tid & 3;

    float acc[NS/4];
#pragma unroll
    for (int i = 0; i < NS/4; i++) acc[i] = 0.f;

    for (int k0 = 0; k0 < C_; k0 += 32) {
#pragma unroll
        for (int e = 0; e < 2; e++) {
            int q  = tid + 256*e;
            int r  = q >> 3;
            int c4 = (q & 7) * 4;
            int m  = m0 + r;
            float4 val;
            if (FUSE) {
                float4 xv = *(const float4*)(A + (size_t)m*C_ + k0 + c4);
                int t = m & (T_-1);
                int b = m >> 11;
                float4 xp = (t > 0) ? *(const float4*)(A + (size_t)(m-1)*C_ + k0 + c4)
                                    : *(const float4*)(shift + (size_t)b*C_ + k0 + c4);
                float4 mx = *(const float4*)(maax + k0 + c4);
                val.x = xv.x + (xp.x - xv.x)*mx.x;
                val.y = xv.y + (xp.y - xv.y)*mx.y;
                val.z = xv.z + (xp.z - xv.z)*mx.z;
                val.w = xv.w + (xp.w - xv.w)*mx.w;
            } else {
                val = *(const float4*)(A + (size_t)m*C_ + k0 + c4);
            }
            As[(c4+0)*68 + r] = val.x;
            As[(c4+1)*68 + r] = val.y;
            As[(c4+2)*68 + r] = val.z;
            As[(c4+3)*68 + r] = val.w;
        }
        {
            const float4* src = (const float4*)(W + (size_t)k0*NS);
            for (int q = tid; q < 32*NS/4; q += 256)
                ((float4*)Ws)[q] = src[q];
        }
        __syncthreads();
#pragma unroll 8
        for (int k = 0; k < 32; k++) {
            float a = As[k*68 + row];
            const float* wrow = Ws + k*NS + cg*(NS/4);
#pragma unroll
            for (int j = 0; j < NS/16; j++) {
                float4 w4 = *(const float4*)(wrow + j*4);
                acc[j*4+0] = fmaf(a, w4.x, acc[j*4+0]);
                acc[j*4+1] = fmaf(a, w4.y, acc[j*4+1]);
                acc[j*4+2] = fmaf(a, w4.z, acc[j*4+2]);
                acc[j*4+3] = fmaf(a, w4.w, acc[j*4+3]);
            }
        }
        __syncthreads();
    }
    float* orow = out + (size_t)(m0+row)*NS + cg*(NS/4);
#pragma unroll
    for (int i = 0; i < NS/4; i++) orow[i] = tanhf(acc[i]);
}

// ---------------- 5-way mix apply, per-f, templated output mode ----------------
// MODE 0: fp16 hi/lo split only.  MODE 1: fp32 only.  MODE 2: fp32 + split.
template<int MODE>
__global__ void __launch_bounds__(256) mix_apply_f(
    const float* __restrict__ x, const float* __restrict__ shift,
    const float* __restrict__ tm, const float* __restrict__ w2,
    const float* __restrict__ maa,
    ushort_t* __restrict__ oh, ushort_t* __restrict__ ol,
    float* __restrict__ of, int f)
{
    __shared__ float tmf[32*32];
    __shared__ float w2f[32*64];
    int tid = threadIdx.x;
    int m0 = blockIdx.y * 32;
    int c0 = blockIdx.x * 64;
    {
        int r = tid >> 3, c4 = (tid & 7) * 4;
        *(float4*)&tmf[r*32 + c4] =
            *(const float4*)(tm + (size_t)(m0+r)*160 + f*32 + c4);
    }
#pragma unroll
    for (int e = 0; e < 2; e++) {
        int q = tid + 256*e;
        int d = q >> 4, c4 = (q & 15) * 4;
        *(float4*)&w2f[d*64 + c4] =
            *(const float4*)(w2 + (size_t)(f*32+d)*C_ + c0 + c4);
    }
    __syncthreads();
#pragma unroll
    for (int e = 0; e < 2; e++) {
        int p = tid + 256*e;
        int r  = p >> 4;
        int c4 = (p & 15) * 4;
        int m = m0 + r;
        int c = c0 + c4;
        float4 acc = make_float4(0.f,0.f,0.f,0.f);
#pragma unroll
        for (int d = 0; d < 32; d++) {
            float tv = tmf[r*32 + d];
            float4 w4 = *(const float4*)&w2f[d*64 + c4];
            acc.x = fmaf(tv, w4.x, acc.x);
            acc.y = fmaf(tv, w4.y, acc.y);
            acc.z = fmaf(tv, w4.z, acc.z);
            acc.w = fmaf(tv, w4.w, acc.w);
        }
        float4 xv = *(const float4*)(x + (size_t)m*C_ + c);
        int t = m & (T_-1), b = m >> 11;
        float4 xp = (t > 0) ? *(const float4*)(x + (size_t)(m-1)*C_ + c)
                            : *(const float4*)(shift + (size_t)b*C_ + c);
        float4 ma = *(const float4*)(maa + c);
        float4 o;
        o.x = xv.x + (xp.x - xv.x)*(ma.x + acc.x);
        o.y = xv.y + (xp.y - xv.y)*(ma.y + acc.y);
        o.z = xv.z + (xp.z - xv.z)*(ma.z + acc.z);
        o.w = xv.w + (xp.w - xv.w)*(ma.w + acc.w);
        size_t base = (size_t)m*C_ + c;
        if (MODE == 1 || MODE == 2)
            *(float4*)(of + base) = o;
        if (MODE == 0 || MODE == 2) {
            ushort4 h4, l4;
            split1(o.x, h4.x, l4.x);
            split1(o.y, h4.y, l4.y);
            split1(o.z, h4.z, l4.z);
            split1(o.w, h4.w, l4.w);
            *(ushort4*)(oh + base) = h4;
            *(ushort4*)(ol + base) = l4;
        }
    }
}

// ---------------- small-K GEMM (K=64) with fused epilogues ----------------
// MODE 0: d = exp(-exp(td + A@W)); store d only (k scaling fused in wkv_scan)
// MODE 1: out1 += A@W
template<int MODE>
__global__ void __launch_bounds__(256) smallk_gemm(
    const float* __restrict__ A, const float* __restrict__ W,
    const float* __restrict__ td, float* __restrict__ out1)
{
    __shared__ float As[32*64];
    __shared__ float Ws[64*128];
    int tid = threadIdx.x;
    int m0 = blockIdx.y * 32, c0 = blockIdx.x * 128;
    {
        const float4* src = (const float4*)(A + (size_t)m0*64);
#pragma unroll
        for (int q = tid; q < 512; q += 256) ((float4*)As)[q] = src[q];
    }
#pragma unroll
    for (int e = 0; e < 8; e++) {
        int q = tid + 256*e;
        int kr = q >> 5, c4 = (q & 31) * 4;
        *(float4*)&Ws[kr*128 + c4] = *(const float4*)(W + (size_t)kr*C_ + c0 + c4);
    }
    __syncthreads();
    int ty = tid >> 4, tx = tid & 15;
    int r0 = ty * 2;
    float acc[2][8];
#pragma unroll
    for (int i = 0; i < 2; i++)
#pragma unroll
        for (int j = 0; j < 8; j++) acc[i][j] = 0.f;
#pragma unroll
    for (int k = 0; k < 64; k++) {
        float a0 = As[r0*64 + k];
        float a1 = As[(r0+1)*64 + k];
        float4 b0 = *(const float4*)&Ws[k*128 + tx*8];
        float4 b1 = *(const float4*)&Ws[k*128 + tx*8 + 4];
        float bv[8] = {b0.x,b0.y,b0.z,b0.w,b1.x,b1.y,b1.z,b1.w};
#pragma unroll
        for (int j = 0; j < 8; j++) {
            acc[0][j] = fmaf(a0, bv[j], acc[0][j]);
            acc[1][j] = fmaf(a1, bv[j], acc[1][j]);
        }
    }
#pragma unroll
    for (int rr = 0; rr < 2; rr++) {
        int m = m0 + r0 + rr;
        size_t base = (size_t)m*C_ + c0 + tx*8;
        if (MODE == 0) {
#pragma unroll
            for (int j = 0; j < 8; j++) {
                float w = td[c0 + tx*8 + j] + acc[rr][j];
                out1[base + j] = expf(-expf(w));
            }
        } else {
#pragma unroll
            for (int j = 0; j < 8; j++) out1[base + j] += acc[rr][j];
        }
    }
}

// ---------------- WKV scan (k*(1-d) fused in) ----------------
__global__ void __launch_bounds__(64) wkv_scan(
    const float* __restrict__ rp, const float* __restrict__ kp,
    const float* __restrict__ vp, const float* __restrict__ dp,
    const float* __restrict__ S0, float* __restrict__ yp,
    float* __restrict__ Sout)
{
    int bh = blockIdx.x;
    int j = threadIdx.x;
    int b = bh >> 5, h = bh & (H_-1);
    float S[64];
    const float* s0 = S0 + (size_t)bh*HS_*HS_ + j;
#pragma unroll
    for (int i = 0; i < 64; i++) S[i] = s0[(size_t)i*64];
    __shared__ float4 skd[64];
    size_t idx = (size_t)b*T_*C_ + (size_t)h*64 + j;
    float rr = rp[idx], kk = kp[idx], dd = dp[idx], vv = vp[idx];
    for (int t = 0; t < T_; t++) {
        float rn = 0.f, kn = 0.f, dn = 0.f, vn = 0.f;
        if (t + 1 < T_) {
            size_t nx = idx + C_;
            rn = rp[nx]; kn = kp[nx]; dn = dp[nx]; vn = vp[nx];
        }
        skd[j] = make_float4(rr, kk * (1.0f - dd), dd, 0.f);
        __syncthreads();
        float acc = 0.f;
#pragma unroll
        for (int i = 0; i < 64; i++) {
            float4 q = skd[i];
            acc  = fmaf(q.x, S[i], acc);
            S[i] = fmaf(q.z, S[i], q.y * vv);
        }
        yp[idx] = acc;
        __syncthreads();
        idx += C_;
        rr = rn; kk = kn; dd = dn; vv = vn;
    }
    float* so = Sout + (size_t)bh*HS_*HS_ + j;
#pragma unroll
    for (int i = 0; i < 64; i++) so[(size_t)i*64] = S[i];
}

// ---------------- fused add + LayerNorm, emits fp16 hi/lo split ----------------
__global__ void __launch_bounds__(256) ln_add_split(
    const float* __restrict__ a, const float* __restrict__ b,
    const float* __restrict__ lw, const float* __restrict__ lb,
    ushort_t* __restrict__ oh, ushort_t* __restrict__ ol)
{
    int m = blockIdx.x;
    int tid = threadIdx.x;
    const float* ar = a + (size_t)m*C_;
    const float* br = b + (size_t)m*C_;
    float vals[8];
    float s = 0.f, s2 = 0.f;
#pragma unroll
    for (int i = 0; i < 8; i++) {
        int c = tid + 256*i;
        float u = ar[c] + br[c];
        vals[i] = u; s += u; s2 = fmaf(u, u, s2);
    }
#pragma unroll
    for (int o = 16; o > 0; o >>= 1) {
        s  += __shfl_xor_sync(0xffffffffu, s,  o);
        s2 += __shfl_xor_sync(0xffffffffu, s2, o);
    }
    __shared__ float sa[8], sb2[8];
    if ((tid & 31) == 0) { sa[tid>>5] = s; sb2[tid>>5] = s2; }
    __syncthreads();
    s = 0.f; s2 = 0.f;
#pragma unroll
    for (int i = 0; i < 8; i++) { s += sa[i]; s2 += sb2[i]; }
    float mu  = s * (1.0f/C_);
    float var = s2 * (1.0f/C_) - mu*mu;
    float inv = rsqrtf(var + 1e-5f);
#pragma unroll
    for (int i = 0; i < 8; i++) {
        int c = tid + 256*i;
        float v = (vals[i] - mu)*inv*lw[c] + lb[c];
        ushort_t h, l;
        split1(v, h, l);
        oh[(size_t)m*C_ + c] = h;
        ol[(size_t)m*C_ + c] = l;
    }
}

__global__ void copy_xlast(const float* __restrict__ x, float* __restrict__ o)
{
    int i = blockIdx.x*256 + threadIdx.x;
    int b = i >> 11, c = i & (C_-1);
    o[i] = x[((size_t)b*T_ + (T_-1))*C_ + c];
}

// ---------------- launcher ----------------
extern "C" void kernel_launch(void* const* d_in, const int* in_sizes, int n_in,
                              void* d_out, int out_size)
{
    (void)in_sizes; (void)n_in;
    const float* x     = (const float*)d_in[0];
    const float* shift = (const float*)d_in[1];
    const float* wkv0  = (const float*)d_in[2];
    const float* maax  = (const float*)d_in[3];
    const float* maar  = (const float*)d_in[4];
    const float* maak  = (const float*)d_in[5];
    const float* maav  = (const float*)d_in[6];
    const float* maaw  = (const float*)d_in[7];
    const float* maav2 = (const float*)d_in[8];
    const float* w1    = (const float*)d_in[9];
    const float* w2    = (const float*)d_in[10];
    const float* tdec  = (const float*)d_in[11];
    const float* dw1   = (const float*)d_in[12];
    const float* dw2   = (const float*)d_in[13];
    const float* vw1   = (const float*)d_in[14];
    const float* vw2   = (const float*)d_in[15];
    const float* Wr    = (const float*)d_in[17];
    const float* Wk    = (const float*)d_in[18];
    const float* Wv    = (const float*)d_in[19];
    const float* Wo    = (const float*)d_in[20];
    const float* lnw   = (const float*)d_in[21];
    const float* lnb   = (const float*)d_in[22];
    float* out = (float*)d_out;

    float *tm,*xrf,*xkf,*xvf,*xw,*xv2,*rb,*kb,*vb,*v2b,*db,*lwv,*lv2,*yw;
    ushort_t *ah,*al,*wr,*wk,*wv,*wo;
    cudaGetSymbolAddress((void**)&tm,  g_tm);
    cudaGetSymbolAddress((void**)&xrf, g_xr);
    cudaGetSymbolAddress((void**)&xkf, g_xk);
    cudaGetSymbolAddress((void**)&xvf, g_xv);
    cudaGetSymbolAddress((void**)&xw,  g_xw);
    cudaGetSymbolAddress((void**)&xv2, g_xv2);
    cudaGetSymbolAddress((void**)&rb,  g_r);
    cudaGetSymbolAddress((void**)&kb,  g_k);
    cudaGetSymbolAddress((void**)&vb,  g_v);
    cudaGetSymbolAddress((void**)&v2b, g_v2);
    cudaGetSymbolAddress((void**)&db,  g_d);
    cudaGetSymbolAddress((void**)&lwv, g_lw);
    cudaGetSymbolAddress((void**)&lv2, g_lv2);
    cudaGetSymbolAddress((void**)&yw,  g_yw);
    cudaGetSymbolAddress((void**)&ah,  g_ah);
    cudaGetSymbolAddress((void**)&al,  g_al);
    cudaGetSymbolAddress((void**)&wr,  g_wr);
    cudaGetSymbolAddress((void**)&wk,  g_wk);
    cudaGetSymbolAddress((void**)&wv,  g_wv);
    cudaGetSymbolAddress((void**)&wo,  g_wo);

    // xr/xk/xv fp32 buffers reinterpreted as fp16 hi/lo pairs
    ushort_t* xrh = (ushort_t*)xrf; ushort_t* xrl = xrh + (size_t)M_*C_;
    ushort_t* xkh = (ushort_t*)xkf; ushort_t* xkl = xkh + (size_t)M_*C_;
    ushort_t* xvh = (ushort_t*)xvf; ushort_t* xvl = xvh + (size_t)M_*C_;

    cudaFuncSetAttribute(gemm_bf3,  cudaFuncAttributeMaxDynamicSharedMemorySize, GEMM_SMEM);
    cudaFuncSetAttribute(gemm_bf3b, cudaFuncAttributeMaxDynamicSharedMemorySize, GEMM_SMEM);

    // 0) weight transpose + fp16 convert
    {
        dim3 gt(C_/32, C_/32);
        wsplit_t<<<gt,256>>>(Wr, wr);
        wsplit_t<<<gt,256>>>(Wk, wk);
        wsplit_t<<<gt,256>>>(Wv, wv);
        wsplit_t<<<gt,256>>>(Wo, wo);
    }

    // 1) LoRA-5 projection with fused token-shift mixing
    skinny_tanh_gemm<160, true><<<M_/64, 256>>>(x, w1, tm, shift, maax);

    // 2) 5-way mix (fp16 split emitted in-kernel)
    {
        dim3 g(C_/64, M_/32);
        mix_apply_f<0><<<g,256>>>(x, shift, tm, w2, maar,  xrh, xrl, nullptr, 0);
        mix_apply_f<0><<<g,256>>>(x, shift, tm, w2, maak,  xkh, xkl, nullptr, 1);
        mix_apply_f<0><<<g,256>>>(x, shift, tm, w2, maav,  xvh, xvl, nullptr, 2);
        mix_apply_f<1><<<g,256>>>(x, shift, tm, w2, maaw,  nullptr, nullptr, xw, 3);
        mix_apply_f<2><<<g,256>>>(x, shift, tm, w2, maav2, ah, al, xv2, 4);
    }

    // 3) big projections via batched HMMA fp16x2 (z = r, k, v, v2)
    {
        GemmBatch gb;
        gb.Ah[0]=xrh; gb.Al[0]=xrl; gb.Bh[0]=wr; gb.Cm[0]=rb;
        gb.Ah[1]=xkh; gb.Al[1]=xkl; gb.Bh[1]=wk; gb.Cm[1]=kb;
        gb.Ah[2]=xvh; gb.Al[2]=xvl; gb.Bh[2]=wv; gb.Cm[2]=vb;
        gb.Ah[3]=ah;  gb.Al[3]=al;  gb.Bh[3]=wv; gb.Cm[3]=v2b;
        dim3 gb4(C_/256, M_/128, 4);
        gemm_bf3b<<<gb4,512,GEMM_SMEM>>>(gb);
    }

    // 4) decay / value2 LoRAs
    skinny_tanh_gemm<64, false><<<M_/64, 256>>>(xw,  dw1, lwv, nullptr, nullptr);
    skinny_tanh_gemm<64, false><<<M_/64, 256>>>(xv2, vw1, lv2, nullptr, nullptr);
    {
        dim3 gs(C_/128, M_/32);
        smallk_gemm<0><<<gs,256>>>(lwv, dw2, tdec, db);      // d only
        smallk_gemm<1><<<gs,256>>>(lv2, vw2, nullptr, v2b);  // v2 += lora
    }

    // 5) WKV scan (k*(1-d) inline), 6) add v2 + LayerNorm, 7) output projection
    const size_t OFFS = (size_t)M_*C_;
    const size_t OFFX = OFFS + (size_t)B_*H_*HS_*HS_;
    bool full = (size_t)out_size >= OFFX + (size_t)B_*C_;
    float* Sout = full ? (out + OFFS) : tm;
    wkv_scan<<<B_*H_, 64>>>(rb, kb, vb, db, wkv0, yw, Sout);
    ln_add_split<<<M_, 256>>>(yw, v2b, lnw, lnb, ah, al);
    dim3 gg(C_/256, M_/128);
    gemm_bf3<<<gg,512,GEMM_SMEM>>>(ah, al, wo, out);
    if (full) copy_xlast<<<(B_*C_)/256, 256>>>(x, out + OFFX);
}